// round 1
// baseline (speedup 1.0000x reference)
#include <cuda_runtime.h>
#include <cfloat>
#include <math.h>

#define NPTS 12000
#define HID  256
#define KNB  16

// ---------------- scratch (allocation-free: __device__ globals) --------------
__device__ float g_h   [NPTS * HID];
__device__ float g_agg [NPTS * HID];
__device__ float g_tmp [NPTS * HID];
__device__ float g_c1  [NPTS * (HID / 2)];
__device__ int   g_nidx[NPTS * KNB];
__device__ float g_nw  [NPTS * KNB];

__device__ __forceinline__ float gelu_f(float x) {
    return 0.5f * x * (1.0f + erff(x * 0.70710678118654752440f));
}

// ---------------- KNN: one warp per row, top-16 by shifted squared dist ------
__global__ void knn_kernel(const float* __restrict__ cents,
                           int* __restrict__ nidx, float* __restrict__ nw) {
    __shared__ float4 tile[1024];
    const int warp = threadIdx.x >> 5;
    const int lane = threadIdx.x & 31;
    const int r = blockIdx.x * 4 + warp;   // 12000 % 4 == 0

    const float xi = cents[2 * r];
    const float yi = cents[2 * r + 1];
    const float n2x = -2.0f * xi;
    const float n2y = -2.0f * yi;

    float vals[KNB];
    int   ids [KNB];
#pragma unroll
    for (int i = 0; i < KNB; ++i) { vals[i] = FLT_MAX; ids[i] = 0; }
    float maxv = FLT_MAX;
    int   maxslot = 0;

    for (int j0 = 0; j0 < NPTS; j0 += 1024) {
        const int cnt = min(1024, NPTS - j0);
        __syncthreads();
        for (int t = threadIdx.x; t < cnt; t += 128) {
            float x = cents[2 * (j0 + t)];
            float y = cents[2 * (j0 + t) + 1];
            tile[t] = make_float4(x, y, fmaf(x, x, y * y), 0.0f);
        }
        __syncthreads();
        for (int c = lane; c < cnt; c += 32) {
            const int j = j0 + c;
            const float4 f = tile[c];
            // shifted squared distance: sq_j - 2*(xi*xj + yi*yj)
            const float d2p = fmaf(n2x, f.x, fmaf(n2y, f.y, f.z));
            if (d2p < maxv && j != r) {
#pragma unroll
                for (int i = 0; i < KNB; ++i)
                    if (i == maxslot) { vals[i] = d2p; ids[i] = j; }
                maxv = vals[0]; maxslot = 0;
#pragma unroll
                for (int i = 1; i < KNB; ++i)
                    if (vals[i] > maxv) { maxv = vals[i]; maxslot = i; }
            }
        }
    }

    // pack into order-preserving u64 keys: mono(float) << 32 | idx (ids unique)
    unsigned long long keys[KNB];
#pragma unroll
    for (int i = 0; i < KNB; ++i) {
        unsigned int u = __float_as_uint(vals[i]);
        u = (u & 0x80000000u) ? ~u : (u | 0x80000000u);
        keys[i] = ((unsigned long long)u << 32) | (unsigned int)ids[i];
    }

    // 16 rounds of warp-wide pop-min over 32x16 register arrays
    unsigned long long sel = 0;
    for (int round = 0; round < KNB; ++round) {
        unsigned long long m = keys[0]; int ms = 0;
#pragma unroll
        for (int i = 1; i < KNB; ++i)
            if (keys[i] < m) { m = keys[i]; ms = i; }
        unsigned long long g = m;
#pragma unroll
        for (int o = 16; o > 0; o >>= 1) {
            unsigned long long t = __shfl_xor_sync(0xffffffffu, g, o);
            if (t < g) g = t;
        }
        if (m == g) {   // unique key -> exactly one winner lane
#pragma unroll
            for (int i = 0; i < KNB; ++i)
                if (i == ms) keys[i] = ~0ull;
        }
        if (lane == round) sel = g;
    }

    // lanes 0..15: recompute exact distance with reference's formula/rounding
    float invd = 0.0f;
    int id = 0;
    if (lane < KNB) {
        id = (int)(sel & 0xffffffffu);
        const float xj = cents[2 * id];
        const float yj = cents[2 * id + 1];
        const float sqi = __fadd_rn(__fmul_rn(xi, xi), __fmul_rn(yi, yi));
        const float sqj = __fadd_rn(__fmul_rn(xj, xj), __fmul_rn(yj, yj));
        const float dot = __fadd_rn(__fmul_rn(xi, xj), __fmul_rn(yi, yj));
        const float d2  = __fsub_rn(__fadd_rn(sqi, sqj), __fmul_rn(2.0f, dot));
        const float dist = sqrtf(fmaxf(d2, 0.0f));
        invd = 1.0f / fmaxf(dist, 1e-4f);
    }
    float tot = invd;
#pragma unroll
    for (int o = 16; o > 0; o >>= 1)
        tot += __shfl_xor_sync(0xffffffffu, tot, o);
    if (lane < KNB) {
        nidx[r * KNB + lane] = id;
        nw  [r * KNB + lane] = invd / fmaxf(tot, 1e-8f);
    }
}

// ---------------- fp32 tiled GEMM: C = act(A@W^T [+ A2@W2^T] [+ bias]) -------
// A: [M,K] row-major, W: [Ncols,K] row-major (i.e. W^T applied), C: [M,Ncols]
template <bool DUAL, bool DOGELU, bool BIAS>
__global__ void gemm_kernel(const float* __restrict__ A, const float* __restrict__ W,
                            const float* __restrict__ A2, const float* __restrict__ W2,
                            const float* __restrict__ bias, float* __restrict__ C,
                            int M, int Ncols, int K) {
    __shared__ float As[16][68];
    __shared__ float Bs[16][68];
    const int tid = threadIdx.x;
    const int tx = tid & 15;
    const int ty = tid >> 4;
    const int m0 = blockIdx.y * 64;
    const int n0 = blockIdx.x * 64;

    const int lm = tid >> 2;          // 0..63
    const int lk = (tid & 3) * 4;     // 0,4,8,12

    float acc[4][4];
#pragma unroll
    for (int i = 0; i < 4; ++i)
#pragma unroll
        for (int j = 0; j < 4; ++j) acc[i][j] = 0.0f;

    const int nsrc = DUAL ? 2 : 1;
    for (int src = 0; src < nsrc; ++src) {
        const float* Ap = (DUAL && src) ? A2 : A;
        const float* Wp = (DUAL && src) ? W2 : W;
        for (int k0 = 0; k0 < K; k0 += 16) {
            float4 av = make_float4(0.f, 0.f, 0.f, 0.f);
            const int gm = m0 + lm;
            if (gm < M)
                av = *reinterpret_cast<const float4*>(Ap + (size_t)gm * K + k0 + lk);
            const float4 bv =
                *reinterpret_cast<const float4*>(Wp + (size_t)(n0 + lm) * K + k0 + lk);
            __syncthreads();
            As[lk + 0][lm] = av.x; As[lk + 1][lm] = av.y;
            As[lk + 2][lm] = av.z; As[lk + 3][lm] = av.w;
            Bs[lk + 0][lm] = bv.x; Bs[lk + 1][lm] = bv.y;
            Bs[lk + 2][lm] = bv.z; Bs[lk + 3][lm] = bv.w;
            __syncthreads();
#pragma unroll
            for (int kk = 0; kk < 16; ++kk) {
                const float4 a = *reinterpret_cast<const float4*>(&As[kk][ty * 4]);
                const float4 b = *reinterpret_cast<const float4*>(&Bs[kk][tx * 4]);
                const float ar[4] = {a.x, a.y, a.z, a.w};
                const float br[4] = {b.x, b.y, b.z, b.w};
#pragma unroll
                for (int i = 0; i < 4; ++i)
#pragma unroll
                    for (int j = 0; j < 4; ++j)
                        acc[i][j] = fmaf(ar[i], br[j], acc[i][j]);
            }
        }
    }

#pragma unroll
    for (int i = 0; i < 4; ++i) {
        const int m = m0 + ty * 4 + i;
        if (m >= M) continue;
#pragma unroll
        for (int j = 0; j < 4; ++j) {
            const int n = n0 + tx * 4 + j;
            float v = acc[i][j];
            if (BIAS) v += bias[n];
            if (DOGELU) v = gelu_f(v);
            C[(size_t)m * Ncols + n] = v;
        }
    }
}

// ---------------- neighbor aggregation: agg[n,d] = sum_k w[n,k]*h[idx[n,k],d]
__global__ void agg_kernel(const float* __restrict__ h, const int* __restrict__ nidx,
                           const float* __restrict__ nw, float* __restrict__ out) {
    const int n = blockIdx.x;
    const int d = threadIdx.x;
    __shared__ int   sidx[KNB];
    __shared__ float sw  [KNB];
    if (d < KNB) { sidx[d] = nidx[n * KNB + d]; sw[d] = nw[n * KNB + d]; }
    __syncthreads();
    float acc = 0.0f;
#pragma unroll
    for (int k = 0; k < KNB; ++k)
        acc = fmaf(sw[k], h[(size_t)sidx[k] * HID + d], acc);
    out[(size_t)n * HID + d] = acc;
}

// ---------------- layernorm + residual: h += LN(x)*g + b ---------------------
__global__ void ln_res_kernel(const float* __restrict__ x, const float* __restrict__ g,
                              const float* __restrict__ b, float* __restrict__ h) {
    const int n = blockIdx.x;
    const int d = threadIdx.x;
    __shared__ float red[8];
    __shared__ float s_mu, s_rstd;

    const float v = x[(size_t)n * HID + d];
    float s = v;
#pragma unroll
    for (int o = 16; o > 0; o >>= 1) s += __shfl_xor_sync(0xffffffffu, s, o);
    if ((d & 31) == 0) red[d >> 5] = s;
    __syncthreads();
    if (d == 0) {
        float t = 0.0f;
        for (int i = 0; i < 8; ++i) t += red[i];
        s_mu = t * (1.0f / HID);
    }
    __syncthreads();
    const float mu = s_mu;
    const float df = v - mu;
    float q = df * df;
#pragma unroll
    for (int o = 16; o > 0; o >>= 1) q += __shfl_xor_sync(0xffffffffu, q, o);
    __syncthreads();               // red reuse guard
    if ((d & 31) == 0) red[d >> 5] = q;
    __syncthreads();
    if (d == 0) {
        float t = 0.0f;
        for (int i = 0; i < 8; ++i) t += red[i];
        s_rstd = rsqrtf(t * (1.0f / HID) + 1e-5f);
    }
    __syncthreads();
    h[(size_t)n * HID + d] = h[(size_t)n * HID + d] + df * s_rstd * g[d] + b[d];
}

// ---------------- classifier layer 2 + sigmoid -------------------------------
__global__ void cls2_kernel(const float* __restrict__ c1, const float* __restrict__ w2,
                            const float* __restrict__ b2, float* __restrict__ out, int M) {
    const int warp = threadIdx.x >> 5;
    const int lane = threadIdx.x & 31;
    const int r = blockIdx.x * 8 + warp;
    if (r >= M) return;
    float s = 0.0f;
#pragma unroll
    for (int j0 = 0; j0 < 128; j0 += 32)
        s = fmaf(c1[(size_t)r * 128 + j0 + lane], w2[j0 + lane], s);
#pragma unroll
    for (int o = 16; o > 0; o >>= 1) s += __shfl_xor_sync(0xffffffffu, s, o);
    if (lane == 0) {
        const float logit = s + b2[0];
        out[r] = 1.0f / (1.0f + expf(-logit));
    }
}

// ---------------- launch ------------------------------------------------------
extern "C" void kernel_launch(void* const* d_in, const int* in_sizes, int n_in,
                              void* d_out, int out_size) {
    const float* feats  = (const float*)d_in[0];
    const float* cents  = (const float*)d_in[1];
    const float* enc_w  = (const float*)d_in[2];
    const float* enc_b  = (const float*)d_in[3];
    const float* g1_ws  = (const float*)d_in[4];
    const float* g1_wn  = (const float*)d_in[5];
    const float* g1_g   = (const float*)d_in[6];
    const float* g1_b   = (const float*)d_in[7];
    const float* g2_ws  = (const float*)d_in[8];
    const float* g2_wn  = (const float*)d_in[9];
    const float* g2_g   = (const float*)d_in[10];
    const float* g2_b   = (const float*)d_in[11];
    const float* cls_w1 = (const float*)d_in[12];
    const float* cls_b1 = (const float*)d_in[13];
    const float* cls_w2 = (const float*)d_in[14];
    const float* cls_b2 = (const float*)d_in[15];
    float* out = (float*)d_out;

    float *p_h, *p_agg, *p_tmp, *p_c1, *p_nw;
    int* p_nidx;
    cudaGetSymbolAddress((void**)&p_h,    g_h);
    cudaGetSymbolAddress((void**)&p_agg,  g_agg);
    cudaGetSymbolAddress((void**)&p_tmp,  g_tmp);
    cudaGetSymbolAddress((void**)&p_c1,   g_c1);
    cudaGetSymbolAddress((void**)&p_nidx, g_nidx);
    cudaGetSymbolAddress((void**)&p_nw,   g_nw);

    const int M = NPTS;
    const dim3 gemm_grid_256(HID / 64, (M + 63) / 64);        // 4 x 188
    const dim3 gemm_grid_128((HID / 2) / 64, (M + 63) / 64);  // 2 x 188

    // KNN graph (independent of encoder)
    knn_kernel<<<NPTS / 4, 128>>>(cents, p_nidx, p_nw);

    // encoder: h = gelu(feats @ enc_w^T + enc_b)
    gemm_kernel<false, true, true><<<gemm_grid_256, 256>>>(
        feats, enc_w, nullptr, nullptr, enc_b, p_h, M, HID, HID);

    // SAGE layer 1
    agg_kernel<<<NPTS, HID>>>(p_h, p_nidx, p_nw, p_agg);
    gemm_kernel<true, true, false><<<gemm_grid_256, 256>>>(
        p_h, g1_ws, p_agg, g1_wn, nullptr, p_tmp, M, HID, HID);
    ln_res_kernel<<<NPTS, HID>>>(p_tmp, g1_g, g1_b, p_h);

    // SAGE layer 2
    agg_kernel<<<NPTS, HID>>>(p_h, p_nidx, p_nw, p_agg);
    gemm_kernel<true, true, false><<<gemm_grid_256, 256>>>(
        p_h, g2_ws, p_agg, g2_wn, nullptr, p_tmp, M, HID, HID);
    ln_res_kernel<<<NPTS, HID>>>(p_tmp, g2_g, g2_b, p_h);

    // classifier
    gemm_kernel<false, true, true><<<gemm_grid_128, 256>>>(
        p_h, cls_w1, nullptr, nullptr, cls_b1, p_c1, M, HID / 2, HID);
    cls2_kernel<<<(M + 7) / 8, 256>>>(p_c1, cls_w2, cls_b2, out, M);
}

// round 2
// speedup vs baseline: 1.3928x; 1.3928x over previous
#include <cuda_runtime.h>
#include <cfloat>
#include <math.h>

#define NPTS 12000
#define HID  256
#define KNB  16
#define G    128
#define NCELL (G * G)

// ---------------- scratch (allocation-free: __device__ globals) --------------
__device__ float g_h   [NPTS * HID];
__device__ float g_agg [NPTS * HID];
__device__ float g_tmp [NPTS * HID];
__device__ float g_c1  [NPTS * (HID / 2)];
__device__ int   g_nidx[NPTS * KNB];
__device__ float g_nw  [NPTS * KNB];

// grid-knn scratch
__device__ unsigned int g_bbox[4];        // xminE, xmaxE, yminE, ymaxE
__device__ int    g_cellcnt [NCELL + 1];  // counts, then scatter cursors
__device__ int    g_cellstart[NCELL + 1];
__device__ float2 g_pts [NPTS];           // cell-sorted coordinates
__device__ int    g_sidx[NPTS];           // sorted slot -> original index

__device__ __forceinline__ float gelu_f(float x) {
    return 0.5f * x * (1.0f + erff(x * 0.70710678118654752440f));
}

// monotone float<->uint encoding for atomic min/max over signed floats
__device__ __forceinline__ unsigned int fenc(float f) {
    unsigned int u = __float_as_uint(f);
    return (u & 0x80000000u) ? ~u : (u | 0x80000000u);
}
__device__ __forceinline__ float fdec(unsigned int u) {
    return __uint_as_float((u & 0x80000000u) ? (u ^ 0x80000000u) : ~u);
}

// ---------------- knn build step 1: init counters + bbox ---------------------
__global__ void knn_init_kernel() {
    const int t = blockIdx.x * blockDim.x + threadIdx.x;
    if (t <= NCELL) { g_cellcnt[t] = 0; }
    if (t == 0) {
        g_bbox[0] = 0xFFFFFFFFu; g_bbox[1] = 0u;
        g_bbox[2] = 0xFFFFFFFFu; g_bbox[3] = 0u;
    }
}

__global__ void knn_bbox_kernel(const float* __restrict__ cents) {
    const int i = blockIdx.x * blockDim.x + threadIdx.x;
    if (i >= NPTS) return;
    const float x = cents[2 * i], y = cents[2 * i + 1];
    atomicMin(&g_bbox[0], fenc(x));
    atomicMax(&g_bbox[1], fenc(x));
    atomicMin(&g_bbox[2], fenc(y));
    atomicMax(&g_bbox[3], fenc(y));
}

__device__ __forceinline__ void grid_params(float& xmin, float& ymin,
                                            float& iwx, float& iwy,
                                            float& wx, float& wy) {
    xmin = fdec(g_bbox[0]);
    const float xmax = fdec(g_bbox[1]);
    ymin = fdec(g_bbox[2]);
    const float ymax = fdec(g_bbox[3]);
    const float rx = fmaxf(xmax - xmin, 1e-20f);
    const float ry = fmaxf(ymax - ymin, 1e-20f);
    iwx = (float)G / rx; iwy = (float)G / ry;
    wx = rx / (float)G;  wy = ry / (float)G;
}

__device__ __forceinline__ int cell_x(float x, float xmin, float iwx) {
    int c = (int)((x - xmin) * iwx);
    return min(max(c, 0), G - 1);
}

// ---------------- step 2: count points per cell -------------------------------
__global__ void knn_count_kernel(const float* __restrict__ cents) {
    const int i = blockIdx.x * blockDim.x + threadIdx.x;
    if (i >= NPTS) return;
    float xmin, ymin, iwx, iwy, wx, wy;
    grid_params(xmin, ymin, iwx, iwy, wx, wy);
    const int cx = cell_x(cents[2 * i],     xmin, iwx);
    const int cy = cell_x(cents[2 * i + 1], ymin, iwy);
    atomicAdd(&g_cellcnt[cy * G + cx], 1);
}

// ---------------- step 3: exclusive prefix scan over 16384 cells --------------
__global__ void knn_scan_kernel() {
    __shared__ int sp[1024];
    const int t = threadIdx.x;
    const int base = t * 16;
    int loc[16];
    int s = 0;
#pragma unroll
    for (int j = 0; j < 16; ++j) { loc[j] = s; s += g_cellcnt[base + j]; }
    sp[t] = s;
    __syncthreads();
    for (int off = 1; off < 1024; off <<= 1) {
        int v = 0;
        if (t >= off) v = sp[t - off];
        __syncthreads();
        if (t >= off) sp[t] += v;
        __syncthreads();
    }
    const int pre = (t == 0) ? 0 : sp[t - 1];
#pragma unroll
    for (int j = 0; j < 16; ++j) {
        g_cellstart[base + j] = pre + loc[j];
        g_cellcnt[base + j]   = pre + loc[j];   // scatter cursor copy
    }
    if (t == 1023) g_cellstart[NCELL] = pre + s;
}

// ---------------- step 4: scatter points into cell-sorted order ---------------
__global__ void knn_scatter_kernel(const float* __restrict__ cents) {
    const int i = blockIdx.x * blockDim.x + threadIdx.x;
    if (i >= NPTS) return;
    float xmin, ymin, iwx, iwy, wx, wy;
    grid_params(xmin, ymin, iwx, iwy, wx, wy);
    const float x = cents[2 * i], y = cents[2 * i + 1];
    const int cx = cell_x(x, xmin, iwx);
    const int cy = cell_x(y, ymin, iwy);
    const int slot = atomicAdd(&g_cellcnt[cy * G + cx], 1);
    g_pts [slot] = make_float2(x, y);
    g_sidx[slot] = i;
}

// ---------------- step 5: per-point ring-expansion query -----------------------
__global__ void knn_query_kernel(const float* __restrict__ cents,
                                 int* __restrict__ nidx, float* __restrict__ nw) {
    const int s = blockIdx.x * blockDim.x + threadIdx.x;
    if (s >= NPTS) return;
    const int i = g_sidx[s];
    const float2 q = g_pts[s];

    float xmin, ymin, iwx, iwy, wx, wy;
    grid_params(xmin, ymin, iwx, iwy, wx, wy);
    const int cx = cell_x(q.x, xmin, iwx);
    const int cy = cell_x(q.y, ymin, iwy);

    float vals[KNB];
    int   ids [KNB];
#pragma unroll
    for (int t = 0; t < KNB; ++t) { vals[t] = FLT_MAX; ids[t] = 0; }
    float maxv = FLT_MAX;
    int   maxslot = 0;

    for (int r = 0; r <= G; ++r) {
        if (r > 0 && maxv < FLT_MAX) {
            // inner square [cx-r+1 .. cx+r-1] fully processed; ring r lies outside
            const float bx1 = q.x - (xmin + (float)(cx - r + 1) * wx);
            const float bx2 = (xmin + (float)(cx + r) * wx) - q.x;
            const float by1 = q.y - (ymin + (float)(cy - r + 1) * wy);
            const float by2 = (ymin + (float)(cy + r) * wy) - q.y;
            const float b = fminf(fminf(bx1, bx2), fminf(by1, by2));
            if (b > 0.0f && b * b > maxv) break;
        }
        const int xlo = max(cx - r, 0), xhi = min(cx + r, G - 1);
        const int ylo = max(cy - r, 0), yhi = min(cy + r, G - 1);
        for (int vy = ylo; vy <= yhi; ++vy) {
            const bool edge_row = (vy == cy - r) || (vy == cy + r);
            int vx = xlo;
            while (vx <= xhi) {
                // on non-edge rows only the two ring columns matter
                if (!edge_row && vx > cx - r && vx < cx + r) { vx = cx + r; continue; }
                const int c = vy * G + vx;
                const int cs = g_cellstart[c];
                const int ce = g_cellstart[c + 1];
                for (int p = cs; p < ce; ++p) {
                    const float2 f = g_pts[p];
                    const float dx = q.x - f.x;
                    const float dy = q.y - f.y;
                    const float d2 = fmaf(dx, dx, dy * dy);
                    if (d2 < maxv && p != s) {
#pragma unroll
                        for (int t = 0; t < KNB; ++t)
                            if (t == maxslot) { vals[t] = d2; ids[t] = g_sidx[p]; }
                        maxv = vals[0]; maxslot = 0;
#pragma unroll
                        for (int t = 1; t < KNB; ++t)
                            if (vals[t] > maxv) { maxv = vals[t]; maxslot = t; }
                    }
                }
                ++vx;
            }
        }
    }

    // re-score winners with the reference's exact formula/rounding
    const float xi = q.x, yi = q.y;
    const float sqi = __fadd_rn(__fmul_rn(xi, xi), __fmul_rn(yi, yi));
    float invd[KNB];
    float tot = 0.0f;
#pragma unroll
    for (int t = 0; t < KNB; ++t) {
        const int id = ids[t];
        const float xj = cents[2 * id];
        const float yj = cents[2 * id + 1];
        const float sqj = __fadd_rn(__fmul_rn(xj, xj), __fmul_rn(yj, yj));
        const float dot = __fadd_rn(__fmul_rn(xi, xj), __fmul_rn(yi, yj));
        const float d2  = __fsub_rn(__fadd_rn(sqi, sqj), __fmul_rn(2.0f, dot));
        const float dist = sqrtf(fmaxf(d2, 0.0f));
        invd[t] = 1.0f / fmaxf(dist, 1e-4f);
        tot += invd[t];
    }
    const float itot = 1.0f / fmaxf(tot, 1e-8f);
#pragma unroll
    for (int t = 0; t < KNB; ++t) {
        nidx[i * KNB + t] = ids[t];
        nw  [i * KNB + t] = invd[t] * itot;
    }
}

// ---------------- fp32 tiled GEMM, 8x8 microtile ------------------------------
// C[M,Ncols] = act(A@W^T [+ A2@W2^T] [+ bias]); W is [Ncols,K] row-major.
// BM=BN=64, BK=16, 64 threads, each computing an 8x8 tile.
template <bool DUAL, bool DOGELU, bool BIAS>
__global__ __launch_bounds__(64) void gemm8_kernel(
    const float* __restrict__ A, const float* __restrict__ W,
    const float* __restrict__ A2, const float* __restrict__ W2,
    const float* __restrict__ bias, float* __restrict__ C,
    int M, int Ncols, int K) {
    __shared__ float As[16][72];
    __shared__ float Bs[16][72];
    const int tid = threadIdx.x;
    const int tx = tid & 7;
    const int ty = tid >> 3;
    const int m0 = blockIdx.y * 64;
    const int n0 = blockIdx.x * 64;

    float acc[8][8];
#pragma unroll
    for (int i = 0; i < 8; ++i)
#pragma unroll
        for (int j = 0; j < 8; ++j) acc[i][j] = 0.0f;

    const int nsrc = DUAL ? 2 : 1;
    for (int src = 0; src < nsrc; ++src) {
        const float* Ap = (DUAL && src) ? A2 : A;
        const float* Wp = (DUAL && src) ? W2 : W;
        for (int k0 = 0; k0 < K; k0 += 16) {
            float4 av[4], bv[4];
            const int gm = m0 + tid;
            const float* arow = Ap + (size_t)gm * K + k0;
            const float* brow = Wp + (size_t)(n0 + tid) * K + k0;
#pragma unroll
            for (int q = 0; q < 4; ++q) {
                av[q] = (gm < M) ? *reinterpret_cast<const float4*>(arow + 4 * q)
                                 : make_float4(0.f, 0.f, 0.f, 0.f);
                bv[q] = *reinterpret_cast<const float4*>(brow + 4 * q);
            }
            __syncthreads();
#pragma unroll
            for (int q = 0; q < 4; ++q) {
                As[4 * q + 0][tid] = av[q].x; As[4 * q + 1][tid] = av[q].y;
                As[4 * q + 2][tid] = av[q].z; As[4 * q + 3][tid] = av[q].w;
                Bs[4 * q + 0][tid] = bv[q].x; Bs[4 * q + 1][tid] = bv[q].y;
                Bs[4 * q + 2][tid] = bv[q].z; Bs[4 * q + 3][tid] = bv[q].w;
            }
            __syncthreads();
#pragma unroll
            for (int kk = 0; kk < 16; ++kk) {
                const float4 a0 = *reinterpret_cast<const float4*>(&As[kk][ty * 8]);
                const float4 a1 = *reinterpret_cast<const float4*>(&As[kk][ty * 8 + 4]);
                const float4 b0 = *reinterpret_cast<const float4*>(&Bs[kk][tx * 8]);
                const float4 b1 = *reinterpret_cast<const float4*>(&Bs[kk][tx * 8 + 4]);
                const float ar[8] = {a0.x, a0.y, a0.z, a0.w, a1.x, a1.y, a1.z, a1.w};
                const float br[8] = {b0.x, b0.y, b0.z, b0.w, b1.x, b1.y, b1.z, b1.w};
#pragma unroll
                for (int i = 0; i < 8; ++i)
#pragma unroll
                    for (int j = 0; j < 8; ++j)
                        acc[i][j] = fmaf(ar[i], br[j], acc[i][j]);
            }
        }
    }

#pragma unroll
    for (int i = 0; i < 8; ++i) {
        const int m = m0 + ty * 8 + i;
        if (m >= M) continue;
        float v[8];
#pragma unroll
        for (int j = 0; j < 8; ++j) {
            v[j] = acc[i][j];
            if (BIAS) v[j] += bias[n0 + tx * 8 + j];
            if (DOGELU) v[j] = gelu_f(v[j]);
        }
        float* crow = C + (size_t)m * Ncols + n0 + tx * 8;
        *reinterpret_cast<float4*>(crow)     = make_float4(v[0], v[1], v[2], v[3]);
        *reinterpret_cast<float4*>(crow + 4) = make_float4(v[4], v[5], v[6], v[7]);
    }
}

// ---------------- neighbor aggregation ----------------------------------------
__global__ void agg_kernel(const float* __restrict__ h, const int* __restrict__ nidx,
                           const float* __restrict__ nw, float* __restrict__ out) {
    const int n = blockIdx.x;
    const int d = threadIdx.x;
    __shared__ int   sidx[KNB];
    __shared__ float sw  [KNB];
    if (d < KNB) { sidx[d] = nidx[n * KNB + d]; sw[d] = nw[n * KNB + d]; }
    __syncthreads();
    float acc = 0.0f;
#pragma unroll
    for (int k = 0; k < KNB; ++k)
        acc = fmaf(sw[k], h[(size_t)sidx[k] * HID + d], acc);
    out[(size_t)n * HID + d] = acc;
}

// ---------------- layernorm + residual -----------------------------------------
__global__ void ln_res_kernel(const float* __restrict__ x, const float* __restrict__ g,
                              const float* __restrict__ b, float* __restrict__ h) {
    const int n = blockIdx.x;
    const int d = threadIdx.x;
    __shared__ float red[8];
    __shared__ float s_mu, s_rstd;

    const float v = x[(size_t)n * HID + d];
    float s = v;
#pragma unroll
    for (int o = 16; o > 0; o >>= 1) s += __shfl_xor_sync(0xffffffffu, s, o);
    if ((d & 31) == 0) red[d >> 5] = s;
    __syncthreads();
    if (d == 0) {
        float t = 0.0f;
        for (int i = 0; i < 8; ++i) t += red[i];
        s_mu = t * (1.0f / HID);
    }
    __syncthreads();
    const float mu = s_mu;
    const float df = v - mu;
    float q = df * df;
#pragma unroll
    for (int o = 16; o > 0; o >>= 1) q += __shfl_xor_sync(0xffffffffu, q, o);
    __syncthreads();
    if ((d & 31) == 0) red[d >> 5] = q;
    __syncthreads();
    if (d == 0) {
        float t = 0.0f;
        for (int i = 0; i < 8; ++i) t += red[i];
        s_rstd = rsqrtf(t * (1.0f / HID) + 1e-5f);
    }
    __syncthreads();
    h[(size_t)n * HID + d] = h[(size_t)n * HID + d] + df * s_rstd * g[d] + b[d];
}

// ---------------- classifier layer 2 + sigmoid ---------------------------------
__global__ void cls2_kernel(const float* __restrict__ c1, const float* __restrict__ w2,
                            const float* __restrict__ b2, float* __restrict__ out, int M) {
    const int warp = threadIdx.x >> 5;
    const int lane = threadIdx.x & 31;
    const int r = blockIdx.x * 8 + warp;
    if (r >= M) return;
    float s = 0.0f;
#pragma unroll
    for (int j0 = 0; j0 < 128; j0 += 32)
        s = fmaf(c1[(size_t)r * 128 + j0 + lane], w2[j0 + lane], s);
#pragma unroll
    for (int o = 16; o > 0; o >>= 1) s += __shfl_xor_sync(0xffffffffu, s, o);
    if (lane == 0) {
        const float logit = s + b2[0];
        out[r] = 1.0f / (1.0f + expf(-logit));
    }
}

// ---------------- launch --------------------------------------------------------
extern "C" void kernel_launch(void* const* d_in, const int* in_sizes, int n_in,
                              void* d_out, int out_size) {
    const float* feats  = (const float*)d_in[0];
    const float* cents  = (const float*)d_in[1];
    const float* enc_w  = (const float*)d_in[2];
    const float* enc_b  = (const float*)d_in[3];
    const float* g1_ws  = (const float*)d_in[4];
    const float* g1_wn  = (const float*)d_in[5];
    const float* g1_g   = (const float*)d_in[6];
    const float* g1_b   = (const float*)d_in[7];
    const float* g2_ws  = (const float*)d_in[8];
    const float* g2_wn  = (const float*)d_in[9];
    const float* g2_g   = (const float*)d_in[10];
    const float* g2_b   = (const float*)d_in[11];
    const float* cls_w1 = (const float*)d_in[12];
    const float* cls_b1 = (const float*)d_in[13];
    const float* cls_w2 = (const float*)d_in[14];
    const float* cls_b2 = (const float*)d_in[15];
    float* out = (float*)d_out;

    float *p_h, *p_agg, *p_tmp, *p_c1, *p_nw;
    int* p_nidx;
    cudaGetSymbolAddress((void**)&p_h,    g_h);
    cudaGetSymbolAddress((void**)&p_agg,  g_agg);
    cudaGetSymbolAddress((void**)&p_tmp,  g_tmp);
    cudaGetSymbolAddress((void**)&p_c1,   g_c1);
    cudaGetSymbolAddress((void**)&p_nidx, g_nidx);
    cudaGetSymbolAddress((void**)&p_nw,   g_nw);

    const int M = NPTS;
    const dim3 g256(HID / 64, (M + 63) / 64);        // 4 x 188
    const dim3 g128((HID / 2) / 64, (M + 63) / 64);  // 2 x 188

    // ---- grid-KNN build + query ----
    knn_init_kernel   <<<(NCELL + 256) / 256, 256>>>();
    knn_bbox_kernel   <<<(NPTS + 255) / 256, 256>>>(cents);
    knn_count_kernel  <<<(NPTS + 255) / 256, 256>>>(cents);
    knn_scan_kernel   <<<1, 1024>>>();
    knn_scatter_kernel<<<(NPTS + 255) / 256, 256>>>(cents);
    knn_query_kernel  <<<(NPTS + 255) / 256, 256>>>(cents, p_nidx, p_nw);

    // encoder: h = gelu(feats @ enc_w^T + enc_b)
    gemm8_kernel<false, true, true><<<g256, 64>>>(
        feats, enc_w, nullptr, nullptr, enc_b, p_h, M, HID, HID);

    // SAGE layer 1
    agg_kernel<<<NPTS, HID>>>(p_h, p_nidx, p_nw, p_agg);
    gemm8_kernel<true, true, false><<<g256, 64>>>(
        p_h, g1_ws, p_agg, g1_wn, nullptr, p_tmp, M, HID, HID);
    ln_res_kernel<<<NPTS, HID>>>(p_tmp, g1_g, g1_b, p_h);

    // SAGE layer 2
    agg_kernel<<<NPTS, HID>>>(p_h, p_nidx, p_nw, p_agg);
    gemm8_kernel<true, true, false><<<g256, 64>>>(
        p_h, g2_ws, p_agg, g2_wn, nullptr, p_tmp, M, HID, HID);
    ln_res_kernel<<<NPTS, HID>>>(p_tmp, g2_g, g2_b, p_h);

    // classifier
    gemm8_kernel<false, true, true><<<g128, 64>>>(
        p_h, cls_w1, nullptr, nullptr, cls_b1, p_c1, M, HID / 2, HID);
    cls2_kernel<<<(M + 7) / 8, 256>>>(p_c1, cls_w2, cls_b2, out, M);
}

// round 3
// speedup vs baseline: 2.3806x; 1.7092x over previous
#include <cuda_runtime.h>
#include <cfloat>
#include <math.h>

#define NPTS 12000
#define HID  256
#define KNB  16
#define G    64
#define NCELL (G * G)

// ---------------- scratch (allocation-free: __device__ globals) --------------
__device__ float g_h   [NPTS * HID];
__device__ float g_agg [NPTS * HID];
__device__ float g_tmp [NPTS * HID];
__device__ float g_c1  [NPTS * (HID / 2)];
__device__ int   g_nidx[NPTS * KNB];
__device__ float g_nw  [NPTS * KNB];

// grid-knn scratch
__device__ unsigned int g_bbox[4];        // xminE, xmaxE, yminE, ymaxE
__device__ int    g_cellcnt [NCELL + 1];  // counts, then scatter cursors
__device__ int    g_cellstart[NCELL + 1];
__device__ float2 g_pts [NPTS];           // cell-sorted coordinates
__device__ int    g_sidx[NPTS];           // sorted slot -> original index

__device__ __forceinline__ float gelu_f(float x) {
    return 0.5f * x * (1.0f + erff(x * 0.70710678118654752440f));
}

__device__ __forceinline__ unsigned int fenc(float f) {
    unsigned int u = __float_as_uint(f);
    return (u & 0x80000000u) ? ~u : (u | 0x80000000u);
}
__device__ __forceinline__ float fdec(unsigned int u) {
    return __uint_as_float((u & 0x80000000u) ? (u ^ 0x80000000u) : ~u);
}

// ---------------- knn build step 1: init counters + bbox ---------------------
__global__ void knn_init_kernel() {
    const int t = blockIdx.x * blockDim.x + threadIdx.x;
    if (t <= NCELL) { g_cellcnt[t] = 0; }
    if (t == 0) {
        g_bbox[0] = 0xFFFFFFFFu; g_bbox[1] = 0u;
        g_bbox[2] = 0xFFFFFFFFu; g_bbox[3] = 0u;
    }
}

__global__ void knn_bbox_kernel(const float* __restrict__ cents) {
    const int i = blockIdx.x * blockDim.x + threadIdx.x;
    if (i >= NPTS) return;
    const float x = cents[2 * i], y = cents[2 * i + 1];
    atomicMin(&g_bbox[0], fenc(x));
    atomicMax(&g_bbox[1], fenc(x));
    atomicMin(&g_bbox[2], fenc(y));
    atomicMax(&g_bbox[3], fenc(y));
}

__device__ __forceinline__ void grid_params(float& xmin, float& ymin,
                                            float& iwx, float& iwy,
                                            float& wx, float& wy) {
    xmin = fdec(g_bbox[0]);
    const float xmax = fdec(g_bbox[1]);
    ymin = fdec(g_bbox[2]);
    const float ymax = fdec(g_bbox[3]);
    const float rx = fmaxf(xmax - xmin, 1e-20f);
    const float ry = fmaxf(ymax - ymin, 1e-20f);
    iwx = (float)G / rx; iwy = (float)G / ry;
    wx = rx / (float)G;  wy = ry / (float)G;
}

__device__ __forceinline__ int cell_x(float x, float xmin, float iwx) {
    int c = (int)((x - xmin) * iwx);
    return min(max(c, 0), G - 1);
}

// ---------------- step 2: count points per cell -------------------------------
__global__ void knn_count_kernel(const float* __restrict__ cents) {
    const int i = blockIdx.x * blockDim.x + threadIdx.x;
    if (i >= NPTS) return;
    float xmin, ymin, iwx, iwy, wx, wy;
    grid_params(xmin, ymin, iwx, iwy, wx, wy);
    const int cx = cell_x(cents[2 * i],     xmin, iwx);
    const int cy = cell_x(cents[2 * i + 1], ymin, iwy);
    atomicAdd(&g_cellcnt[cy * G + cx], 1);
}

// ---------------- step 3: exclusive prefix scan over 4096 cells ---------------
// 256 threads x 16 cells, two-level warp scan.
__global__ void knn_scan_kernel() {
    __shared__ int wsum[8];
    const int t = threadIdx.x;
    const int lane = t & 31;
    const int warp = t >> 5;
    const int base = t * 16;
    int loc[16];
    int s = 0;
#pragma unroll
    for (int j = 0; j < 16; ++j) { loc[j] = s; s += g_cellcnt[base + j]; }
    int v = s;  // inclusive warp scan
#pragma unroll
    for (int off = 1; off < 32; off <<= 1) {
        const int n = __shfl_up_sync(0xffffffffu, v, off);
        if (lane >= off) v += n;
    }
    if (lane == 31) wsum[warp] = v;
    __syncthreads();
    if (t == 0) {
        int run = 0;
        for (int i = 0; i < 8; ++i) { const int tmp = wsum[i]; wsum[i] = run; run += tmp; }
    }
    __syncthreads();
    const int pre = wsum[warp] + (v - s);
#pragma unroll
    for (int j = 0; j < 16; ++j) {
        g_cellstart[base + j] = pre + loc[j];
        g_cellcnt[base + j]   = pre + loc[j];   // scatter cursor copy
    }
    if (t == 255) g_cellstart[NCELL] = NPTS;
}

// ---------------- step 4: scatter points into cell-sorted order ---------------
__global__ void knn_scatter_kernel(const float* __restrict__ cents) {
    const int i = blockIdx.x * blockDim.x + threadIdx.x;
    if (i >= NPTS) return;
    float xmin, ymin, iwx, iwy, wx, wy;
    grid_params(xmin, ymin, iwx, iwy, wx, wy);
    const float x = cents[2 * i], y = cents[2 * i + 1];
    const int cx = cell_x(x, xmin, iwx);
    const int cy = cell_x(y, ymin, iwy);
    const int slot = atomicAdd(&g_cellcnt[cy * G + cx], 1);
    g_pts [slot] = make_float2(x, y);
    g_sidx[slot] = i;
}

// ---------------- step 5: warp-per-query ring expansion -----------------------
// All 32 lanes hold a REPLICATED top-16 (identical registers in every lane).
// Candidates are evaluated 32 at a time; rare acceptances are serialized via
// ballot and inserted identically in all lanes (no divergence).
__global__ void knn_query_kernel(int* __restrict__ nidx, float* __restrict__ nw) {
    const int w = (blockIdx.x * blockDim.x + threadIdx.x) >> 5;
    const int lane = threadIdx.x & 31;
    if (w >= NPTS) return;
    const int s = w;                 // sorted slot = query
    const float2 q = g_pts[s];
    const int i = g_sidx[s];

    float xmin, ymin, iwx, iwy, wx, wy;
    grid_params(xmin, ymin, iwx, iwy, wx, wy);
    const int cx = cell_x(q.x, xmin, iwx);
    const int cy = cell_x(q.y, ymin, iwy);

    float vals[KNB];
    int   ids [KNB];                 // stores sorted SLOT of the neighbor
#pragma unroll
    for (int t = 0; t < KNB; ++t) { vals[t] = FLT_MAX; ids[t] = 0; }
    float maxv = FLT_MAX;
    int   maxslot = 0;

    for (int r = 0; r < G; ++r) {
        const int ylo = max(cy - r, 0), yhi = min(cy + r, G - 1);
        for (int vy = ylo; vy <= yhi; ++vy) {
            const bool edge_row = (vy == cy - r) || (vy == cy + r);
            // up to 2 contiguous slot-ranges for this row of the ring
            int ps0 = 0, pe0 = 0, ps1 = 0, pe1 = 0;
            if (edge_row) {
                const int xl = max(cx - r, 0), xh = min(cx + r, G - 1);
                ps0 = g_cellstart[vy * G + xl];
                pe0 = g_cellstart[vy * G + xh + 1];
            } else {
                if (cx - r >= 0) {
                    ps0 = g_cellstart[vy * G + cx - r];
                    pe0 = g_cellstart[vy * G + cx - r + 1];
                }
                if (cx + r <= G - 1) {
                    ps1 = g_cellstart[vy * G + cx + r];
                    pe1 = g_cellstart[vy * G + cx + r + 1];
                }
            }
#pragma unroll
            for (int seg = 0; seg < 2; ++seg) {
                const int ps = seg ? ps1 : ps0;
                const int pe = seg ? pe1 : pe0;
                for (int p0 = ps; p0 < pe; p0 += 32) {
                    const int p = p0 + lane;
                    float d2 = FLT_MAX;
                    if (p < pe && p != s) {
                        const float2 f = g_pts[p];
                        const float dx = q.x - f.x;
                        const float dy = q.y - f.y;
                        d2 = fmaf(dx, dx, dy * dy);
                    }
                    unsigned int m = __ballot_sync(0xffffffffu, d2 < maxv);
                    while (m) {
                        const int l = __ffs(m) - 1;
                        m &= m - 1;
                        const float dd = __shfl_sync(0xffffffffu, d2, l);
                        if (dd < maxv) {
                            const int pp = __shfl_sync(0xffffffffu, p, l);
#pragma unroll
                            for (int t = 0; t < KNB; ++t)
                                if (t == maxslot) { vals[t] = dd; ids[t] = pp; }
                            maxv = vals[0]; maxslot = 0;
#pragma unroll
                            for (int t = 1; t < KNB; ++t)
                                if (vals[t] > maxv) { maxv = vals[t]; maxslot = t; }
                        }
                    }
                }
            }
        }
        // full square of radius r processed; exact termination bound
        if (maxv < FLT_MAX) {
            const float bl = (cx - r > 0)     ? q.x - (xmin + (float)(cx - r) * wx)     : FLT_MAX;
            const float br = (cx + r < G - 1) ? (xmin + (float)(cx + r + 1) * wx) - q.x : FLT_MAX;
            const float bb = (cy - r > 0)     ? q.y - (ymin + (float)(cy - r) * wy)     : FLT_MAX;
            const float bt = (cy + r < G - 1) ? (ymin + (float)(cy + r + 1) * wy) - q.y : FLT_MAX;
            const float b = fminf(fminf(bl, br), fminf(bb, bt));
            if (b == FLT_MAX || (b > 0.0f && b * b > maxv)) break;
        }
    }

    // distribute replicated slots to lanes 0..15 and rescore with the
    // reference's exact formula/rounding
    int myslot = 0;
#pragma unroll
    for (int t = 0; t < KNB; ++t)
        if (t == lane) myslot = ids[t];

    float invd = 0.0f;
    int oid = 0;
    if (lane < KNB) {
        const float2 f = g_pts[myslot];
        oid = g_sidx[myslot];
        const float xi = q.x, yi = q.y;
        const float sqi = __fadd_rn(__fmul_rn(xi, xi), __fmul_rn(yi, yi));
        const float sqj = __fadd_rn(__fmul_rn(f.x, f.x), __fmul_rn(f.y, f.y));
        const float dot = __fadd_rn(__fmul_rn(xi, f.x), __fmul_rn(yi, f.y));
        const float d2  = __fsub_rn(__fadd_rn(sqi, sqj), __fmul_rn(2.0f, dot));
        const float dist = sqrtf(fmaxf(d2, 0.0f));
        invd = 1.0f / fmaxf(dist, 1e-4f);
    }
    float tot = invd;
#pragma unroll
    for (int o = 16; o > 0; o >>= 1)
        tot += __shfl_xor_sync(0xffffffffu, tot, o);
    if (lane < KNB) {
        nidx[i * KNB + lane] = oid;
        nw  [i * KNB + lane] = invd / fmaxf(tot, 1e-8f);
    }
}

// ---------------- fp32 tiled GEMM, 8x8 microtile ------------------------------
template <bool DUAL, bool DOGELU, bool BIAS>
__global__ __launch_bounds__(64) void gemm8_kernel(
    const float* __restrict__ A, const float* __restrict__ W,
    const float* __restrict__ A2, const float* __restrict__ W2,
    const float* __restrict__ bias, float* __restrict__ C,
    int M, int Ncols, int K) {
    __shared__ float As[16][72];
    __shared__ float Bs[16][72];
    const int tid = threadIdx.x;
    const int tx = tid & 7;
    const int ty = tid >> 3;
    const int m0 = blockIdx.y * 64;
    const int n0 = blockIdx.x * 64;

    float acc[8][8];
#pragma unroll
    for (int i = 0; i < 8; ++i)
#pragma unroll
        for (int j = 0; j < 8; ++j) acc[i][j] = 0.0f;

    const int nsrc = DUAL ? 2 : 1;
    for (int src = 0; src < nsrc; ++src) {
        const float* Ap = (DUAL && src) ? A2 : A;
        const float* Wp = (DUAL && src) ? W2 : W;
        for (int k0 = 0; k0 < K; k0 += 16) {
            float4 av[4], bv[4];
            const int gm = m0 + tid;
            const float* arow = Ap + (size_t)gm * K + k0;
            const float* brow = Wp + (size_t)(n0 + tid) * K + k0;
#pragma unroll
            for (int q = 0; q < 4; ++q) {
                av[q] = (gm < M) ? *reinterpret_cast<const float4*>(arow + 4 * q)
                                 : make_float4(0.f, 0.f, 0.f, 0.f);
                bv[q] = *reinterpret_cast<const float4*>(brow + 4 * q);
            }
            __syncthreads();
#pragma unroll
            for (int q = 0; q < 4; ++q) {
                As[4 * q + 0][tid] = av[q].x; As[4 * q + 1][tid] = av[q].y;
                As[4 * q + 2][tid] = av[q].z; As[4 * q + 3][tid] = av[q].w;
                Bs[4 * q + 0][tid] = bv[q].x; Bs[4 * q + 1][tid] = bv[q].y;
                Bs[4 * q + 2][tid] = bv[q].z; Bs[4 * q + 3][tid] = bv[q].w;
            }
            __syncthreads();
#pragma unroll
            for (int kk = 0; kk < 16; ++kk) {
                const float4 a0 = *reinterpret_cast<const float4*>(&As[kk][ty * 8]);
                const float4 a1 = *reinterpret_cast<const float4*>(&As[kk][ty * 8 + 4]);
                const float4 b0 = *reinterpret_cast<const float4*>(&Bs[kk][tx * 8]);
                const float4 b1 = *reinterpret_cast<const float4*>(&Bs[kk][tx * 8 + 4]);
                const float ar[8] = {a0.x, a0.y, a0.z, a0.w, a1.x, a1.y, a1.z, a1.w};
                const float br[8] = {b0.x, b0.y, b0.z, b0.w, b1.x, b1.y, b1.z, b1.w};
#pragma unroll
                for (int i = 0; i < 8; ++i)
#pragma unroll
                    for (int j = 0; j < 8; ++j)
                        acc[i][j] = fmaf(ar[i], br[j], acc[i][j]);
            }
        }
    }

#pragma unroll
    for (int i = 0; i < 8; ++i) {
        const int m = m0 + ty * 8 + i;
        if (m >= M) continue;
        float v[8];
#pragma unroll
        for (int j = 0; j < 8; ++j) {
            v[j] = acc[i][j];
            if (BIAS) v[j] += bias[n0 + tx * 8 + j];
            if (DOGELU) v[j] = gelu_f(v[j]);
        }
        float* crow = C + (size_t)m * Ncols + n0 + tx * 8;
        *reinterpret_cast<float4*>(crow)     = make_float4(v[0], v[1], v[2], v[3]);
        *reinterpret_cast<float4*>(crow + 4) = make_float4(v[4], v[5], v[6], v[7]);
    }
}

// ---------------- neighbor aggregation ----------------------------------------
__global__ void agg_kernel(const float* __restrict__ h, const int* __restrict__ nidx,
                           const float* __restrict__ nw, float* __restrict__ out) {
    const int n = blockIdx.x;
    const int d = threadIdx.x;
    __shared__ int   sidx[KNB];
    __shared__ float sw  [KNB];
    if (d < KNB) { sidx[d] = nidx[n * KNB + d]; sw[d] = nw[n * KNB + d]; }
    __syncthreads();
    float acc = 0.0f;
#pragma unroll
    for (int k = 0; k < KNB; ++k)
        acc = fmaf(sw[k], h[(size_t)sidx[k] * HID + d], acc);
    out[(size_t)n * HID + d] = acc;
}

// ---------------- layernorm + residual -----------------------------------------
__global__ void ln_res_kernel(const float* __restrict__ x, const float* __restrict__ g,
                              const float* __restrict__ b, float* __restrict__ h) {
    const int n = blockIdx.x;
    const int d = threadIdx.x;
    __shared__ float red[8];
    __shared__ float s_mu, s_rstd;

    const float v = x[(size_t)n * HID + d];
    float s = v;
#pragma unroll
    for (int o = 16; o > 0; o >>= 1) s += __shfl_xor_sync(0xffffffffu, s, o);
    if ((d & 31) == 0) red[d >> 5] = s;
    __syncthreads();
    if (d == 0) {
        float t = 0.0f;
        for (int i = 0; i < 8; ++i) t += red[i];
        s_mu = t * (1.0f / HID);
    }
    __syncthreads();
    const float mu = s_mu;
    const float df = v - mu;
    float q = df * df;
#pragma unroll
    for (int o = 16; o > 0; o >>= 1) q += __shfl_xor_sync(0xffffffffu, q, o);
    __syncthreads();
    if ((d & 31) == 0) red[d >> 5] = q;
    __syncthreads();
    if (d == 0) {
        float t = 0.0f;
        for (int i = 0; i < 8; ++i) t += red[i];
        s_rstd = rsqrtf(t * (1.0f / HID) + 1e-5f);
    }
    __syncthreads();
    h[(size_t)n * HID + d] = h[(size_t)n * HID + d] + df * s_rstd * g[d] + b[d];
}

// ---------------- classifier layer 2 + sigmoid ---------------------------------
__global__ void cls2_kernel(const float* __restrict__ c1, const float* __restrict__ w2,
                            const float* __restrict__ b2, float* __restrict__ out, int M) {
    const int warp = threadIdx.x >> 5;
    const int lane = threadIdx.x & 31;
    const int r = blockIdx.x * 8 + warp;
    if (r >= M) return;
    float s = 0.0f;
#pragma unroll
    for (int j0 = 0; j0 < 128; j0 += 32)
        s = fmaf(c1[(size_t)r * 128 + j0 + lane], w2[j0 + lane], s);
#pragma unroll
    for (int o = 16; o > 0; o >>= 1) s += __shfl_xor_sync(0xffffffffu, s, o);
    if (lane == 0) {
        const float logit = s + b2[0];
        out[r] = 1.0f / (1.0f + expf(-logit));
    }
}

// ---------------- launch --------------------------------------------------------
extern "C" void kernel_launch(void* const* d_in, const int* in_sizes, int n_in,
                              void* d_out, int out_size) {
    const float* feats  = (const float*)d_in[0];
    const float* cents  = (const float*)d_in[1];
    const float* enc_w  = (const float*)d_in[2];
    const float* enc_b  = (const float*)d_in[3];
    const float* g1_ws  = (const float*)d_in[4];
    const float* g1_wn  = (const float*)d_in[5];
    const float* g1_g   = (const float*)d_in[6];
    const float* g1_b   = (const float*)d_in[7];
    const float* g2_ws  = (const float*)d_in[8];
    const float* g2_wn  = (const float*)d_in[9];
    const float* g2_g   = (const float*)d_in[10];
    const float* g2_b   = (const float*)d_in[11];
    const float* cls_w1 = (const float*)d_in[12];
    const float* cls_b1 = (const float*)d_in[13];
    const float* cls_w2 = (const float*)d_in[14];
    const float* cls_b2 = (const float*)d_in[15];
    float* out = (float*)d_out;

    float *p_h, *p_agg, *p_tmp, *p_c1, *p_nw;
    int* p_nidx;
    cudaGetSymbolAddress((void**)&p_h,    g_h);
    cudaGetSymbolAddress((void**)&p_agg,  g_agg);
    cudaGetSymbolAddress((void**)&p_tmp,  g_tmp);
    cudaGetSymbolAddress((void**)&p_c1,   g_c1);
    cudaGetSymbolAddress((void**)&p_nidx, g_nidx);
    cudaGetSymbolAddress((void**)&p_nw,   g_nw);

    const int M = NPTS;
    const dim3 g256(HID / 64, (M + 63) / 64);        // 4 x 188
    const dim3 g128((HID / 2) / 64, (M + 63) / 64);  // 2 x 188

    // ---- grid-KNN build + query ----
    knn_init_kernel   <<<(NCELL + 256) / 256, 256>>>();
    knn_bbox_kernel   <<<(NPTS + 255) / 256, 256>>>(cents);
    knn_count_kernel  <<<(NPTS + 255) / 256, 256>>>(cents);
    knn_scan_kernel   <<<1, 256>>>();
    knn_scatter_kernel<<<(NPTS + 255) / 256, 256>>>(cents);
    knn_query_kernel  <<<(NPTS * 32 + 255) / 256, 256>>>(p_nidx, p_nw);

    // encoder: h = gelu(feats @ enc_w^T + enc_b)
    gemm8_kernel<false, true, true><<<g256, 64>>>(
        feats, enc_w, nullptr, nullptr, enc_b, p_h, M, HID, HID);

    // SAGE layer 1
    agg_kernel<<<NPTS, HID>>>(p_h, p_nidx, p_nw, p_agg);
    gemm8_kernel<true, true, false><<<g256, 64>>>(
        p_h, g1_ws, p_agg, g1_wn, nullptr, p_tmp, M, HID, HID);
    ln_res_kernel<<<NPTS, HID>>>(p_tmp, g1_g, g1_b, p_h);

    // SAGE layer 2
    agg_kernel<<<NPTS, HID>>>(p_h, p_nidx, p_nw, p_agg);
    gemm8_kernel<true, true, false><<<g256, 64>>>(
        p_h, g2_ws, p_agg, g2_wn, nullptr, p_tmp, M, HID, HID);
    ln_res_kernel<<<NPTS, HID>>>(p_tmp, g2_g, g2_b, p_h);

    // classifier
    gemm8_kernel<false, true, true><<<g128, 64>>>(
        p_h, cls_w1, nullptr, nullptr, cls_b1, p_c1, M, HID / 2, HID);
    cls2_kernel<<<(M + 7) / 8, 256>>>(p_c1, cls_w2, cls_b2, out, M);
}

// round 6
// speedup vs baseline: 2.9910x; 1.2564x over previous
#include <cuda_runtime.h>
#include <cuda_bf16.h>
#include <cstdint>
#include <cfloat>
#include <math.h>

#define NPTS 12000
#define HID  256
#define KNB  16
#define G    64
#define NCELL (G * G)

// ---------------- scratch (allocation-free: __device__ globals) --------------
__device__ float g_h   [NPTS * HID];
__device__ float g_tmp [NPTS * HID];
__device__ float g_c1  [NPTS * (HID / 2)];
__device__ int   g_nidx[NPTS * KNB];
__device__ float g_nw  [NPTS * KNB];

// bf16 split operand buffers
__device__ __nv_bfloat16 g_fh[NPTS * HID], g_fl[NPTS * HID];   // feats split
__device__ __nv_bfloat16 g_ah[NPTS * HID], g_al[NPTS * HID];   // h split
__device__ __nv_bfloat16 g_gh[NPTS * HID], g_gl[NPTS * HID];   // agg split
#define WTOT 360448
__device__ __nv_bfloat16 g_wh[WTOT], g_wl[WTOT];
// slots: enc=0, g1ws=65536, g1wn=131072, g2ws=196608, g2wn=262144, cls=327680

// grid-knn scratch
__device__ unsigned int g_bbox[4];
__device__ int    g_cellcnt [NCELL + 1];
__device__ int    g_cellstart[NCELL + 1];
__device__ float2 g_pts [NPTS];
__device__ int    g_sidx[NPTS];

__device__ __forceinline__ float gelu_f(float x) {
    return 0.5f * x * (1.0f + erff(x * 0.70710678118654752440f));
}

__device__ __forceinline__ unsigned int fenc(float f) {
    unsigned int u = __float_as_uint(f);
    return (u & 0x80000000u) ? ~u : (u | 0x80000000u);
}
__device__ __forceinline__ float fdec(unsigned int u) {
    return __uint_as_float((u & 0x80000000u) ? (u ^ 0x80000000u) : ~u);
}

// HMMA: D(f32) += A(bf16,row) * B(bf16,col), m16n8k16
__device__ __forceinline__ void mma16816(float* c, const uint32_t* a, const uint32_t* b) {
    asm volatile(
        "mma.sync.aligned.m16n8k16.row.col.f32.bf16.bf16.f32 "
        "{%0,%1,%2,%3}, {%4,%5,%6,%7}, {%8,%9}, {%0,%1,%2,%3};"
        : "+f"(c[0]), "+f"(c[1]), "+f"(c[2]), "+f"(c[3])
        : "r"(a[0]), "r"(a[1]), "r"(a[2]), "r"(a[3]), "r"(b[0]), "r"(b[1]));
}

// ================= KNN (unchanged from round 3) ================================
__global__ void knn_init_kernel() {
    const int t = blockIdx.x * blockDim.x + threadIdx.x;
    if (t <= NCELL) { g_cellcnt[t] = 0; }
    if (t == 0) {
        g_bbox[0] = 0xFFFFFFFFu; g_bbox[1] = 0u;
        g_bbox[2] = 0xFFFFFFFFu; g_bbox[3] = 0u;
    }
}

__global__ void knn_bbox_kernel(const float* __restrict__ cents) {
    const int i = blockIdx.x * blockDim.x + threadIdx.x;
    if (i >= NPTS) return;
    const float x = cents[2 * i], y = cents[2 * i + 1];
    atomicMin(&g_bbox[0], fenc(x));
    atomicMax(&g_bbox[1], fenc(x));
    atomicMin(&g_bbox[2], fenc(y));
    atomicMax(&g_bbox[3], fenc(y));
}

__device__ __forceinline__ void grid_params(float& xmin, float& ymin,
                                            float& iwx, float& iwy,
                                            float& wx, float& wy) {
    xmin = fdec(g_bbox[0]);
    const float xmax = fdec(g_bbox[1]);
    ymin = fdec(g_bbox[2]);
    const float ymax = fdec(g_bbox[3]);
    const float rx = fmaxf(xmax - xmin, 1e-20f);
    const float ry = fmaxf(ymax - ymin, 1e-20f);
    iwx = (float)G / rx; iwy = (float)G / ry;
    wx = rx / (float)G;  wy = ry / (float)G;
}

__device__ __forceinline__ int cell_x(float x, float xmin, float iwx) {
    int c = (int)((x - xmin) * iwx);
    return min(max(c, 0), G - 1);
}

__global__ void knn_count_kernel(const float* __restrict__ cents) {
    const int i = blockIdx.x * blockDim.x + threadIdx.x;
    if (i >= NPTS) return;
    float xmin, ymin, iwx, iwy, wx, wy;
    grid_params(xmin, ymin, iwx, iwy, wx, wy);
    const int cx = cell_x(cents[2 * i],     xmin, iwx);
    const int cy = cell_x(cents[2 * i + 1], ymin, iwy);
    atomicAdd(&g_cellcnt[cy * G + cx], 1);
}

__global__ void knn_scan_kernel() {
    __shared__ int wsum[8];
    const int t = threadIdx.x;
    const int lane = t & 31;
    const int warp = t >> 5;
    const int base = t * 16;
    int loc[16];
    int s = 0;
#pragma unroll
    for (int j = 0; j < 16; ++j) { loc[j] = s; s += g_cellcnt[base + j]; }
    int v = s;
#pragma unroll
    for (int off = 1; off < 32; off <<= 1) {
        const int n = __shfl_up_sync(0xffffffffu, v, off);
        if (lane >= off) v += n;
    }
    if (lane == 31) wsum[warp] = v;
    __syncthreads();
    if (t == 0) {
        int run = 0;
        for (int i = 0; i < 8; ++i) { const int tmp = wsum[i]; wsum[i] = run; run += tmp; }
    }
    __syncthreads();
    const int pre = wsum[warp] + (v - s);
#pragma unroll
    for (int j = 0; j < 16; ++j) {
        g_cellstart[base + j] = pre + loc[j];
        g_cellcnt[base + j]   = pre + loc[j];
    }
    if (t == 255) g_cellstart[NCELL] = NPTS;
}

__global__ void knn_scatter_kernel(const float* __restrict__ cents) {
    const int i = blockIdx.x * blockDim.x + threadIdx.x;
    if (i >= NPTS) return;
    float xmin, ymin, iwx, iwy, wx, wy;
    grid_params(xmin, ymin, iwx, iwy, wx, wy);
    const float x = cents[2 * i], y = cents[2 * i + 1];
    const int cx = cell_x(x, xmin, iwx);
    const int cy = cell_x(y, ymin, iwy);
    const int slot = atomicAdd(&g_cellcnt[cy * G + cx], 1);
    g_pts [slot] = make_float2(x, y);
    g_sidx[slot] = i;
}

__global__ void knn_query_kernel(int* __restrict__ nidx, float* __restrict__ nw) {
    const int w = (blockIdx.x * blockDim.x + threadIdx.x) >> 5;
    const int lane = threadIdx.x & 31;
    if (w >= NPTS) return;
    const int s = w;
    const float2 q = g_pts[s];
    const int i = g_sidx[s];

    float xmin, ymin, iwx, iwy, wx, wy;
    grid_params(xmin, ymin, iwx, iwy, wx, wy);
    const int cx = cell_x(q.x, xmin, iwx);
    const int cy = cell_x(q.y, ymin, iwy);

    float vals[KNB];
    int   ids [KNB];
#pragma unroll
    for (int t = 0; t < KNB; ++t) { vals[t] = FLT_MAX; ids[t] = 0; }
    float maxv = FLT_MAX;
    int   maxslot = 0;

    for (int r = 0; r < G; ++r) {
        const int ylo = max(cy - r, 0), yhi = min(cy + r, G - 1);
        for (int vy = ylo; vy <= yhi; ++vy) {
            const bool edge_row = (vy == cy - r) || (vy == cy + r);
            int ps0 = 0, pe0 = 0, ps1 = 0, pe1 = 0;
            if (edge_row) {
                const int xl = max(cx - r, 0), xh = min(cx + r, G - 1);
                ps0 = g_cellstart[vy * G + xl];
                pe0 = g_cellstart[vy * G + xh + 1];
            } else {
                if (cx - r >= 0) {
                    ps0 = g_cellstart[vy * G + cx - r];
                    pe0 = g_cellstart[vy * G + cx - r + 1];
                }
                if (cx + r <= G - 1) {
                    ps1 = g_cellstart[vy * G + cx + r];
                    pe1 = g_cellstart[vy * G + cx + r + 1];
                }
            }
#pragma unroll
            for (int seg = 0; seg < 2; ++seg) {
                const int ps = seg ? ps1 : ps0;
                const int pe = seg ? pe1 : pe0;
                for (int p0 = ps; p0 < pe; p0 += 32) {
                    const int p = p0 + lane;
                    float d2 = FLT_MAX;
                    if (p < pe && p != s) {
                        const float2 f = g_pts[p];
                        const float dx = q.x - f.x;
                        const float dy = q.y - f.y;
                        d2 = fmaf(dx, dx, dy * dy);
                    }
                    unsigned int m = __ballot_sync(0xffffffffu, d2 < maxv);
                    while (m) {
                        const int l = __ffs(m) - 1;
                        m &= m - 1;
                        const float dd = __shfl_sync(0xffffffffu, d2, l);
                        if (dd < maxv) {
                            const int pp = __shfl_sync(0xffffffffu, p, l);
#pragma unroll
                            for (int t = 0; t < KNB; ++t)
                                if (t == maxslot) { vals[t] = dd; ids[t] = pp; }
                            maxv = vals[0]; maxslot = 0;
#pragma unroll
                            for (int t = 1; t < KNB; ++t)
                                if (vals[t] > maxv) { maxv = vals[t]; maxslot = t; }
                        }
                    }
                }
            }
        }
        if (maxv < FLT_MAX) {
            const float bl = (cx - r > 0)     ? q.x - (xmin + (float)(cx - r) * wx)     : FLT_MAX;
            const float br = (cx + r < G - 1) ? (xmin + (float)(cx + r + 1) * wx) - q.x : FLT_MAX;
            const float bb = (cy - r > 0)     ? q.y - (ymin + (float)(cy - r) * wy)     : FLT_MAX;
            const float bt = (cy + r < G - 1) ? (ymin + (float)(cy + r + 1) * wy) - q.y : FLT_MAX;
            const float b = fminf(fminf(bl, br), fminf(bb, bt));
            if (b == FLT_MAX || (b > 0.0f && b * b > maxv)) break;
        }
    }

    int myslot = 0;
#pragma unroll
    for (int t = 0; t < KNB; ++t)
        if (t == lane) myslot = ids[t];

    float invd = 0.0f;
    int oid = 0;
    if (lane < KNB) {
        const float2 f = g_pts[myslot];
        oid = g_sidx[myslot];
        const float xi = q.x, yi = q.y;
        const float sqi = __fadd_rn(__fmul_rn(xi, xi), __fmul_rn(yi, yi));
        const float sqj = __fadd_rn(__fmul_rn(f.x, f.x), __fmul_rn(f.y, f.y));
        const float dot = __fadd_rn(__fmul_rn(xi, f.x), __fmul_rn(yi, f.y));
        const float d2  = __fsub_rn(__fadd_rn(sqi, sqj), __fmul_rn(2.0f, dot));
        const float dist = sqrtf(fmaxf(d2, 0.0f));
        invd = 1.0f / fmaxf(dist, 1e-4f);
    }
    float tot = invd;
#pragma unroll
    for (int o = 16; o > 0; o >>= 1)
        tot += __shfl_xor_sync(0xffffffffu, tot, o);
    if (lane < KNB) {
        nidx[i * KNB + lane] = oid;
        nw  [i * KNB + lane] = invd / fmaxf(tot, 1e-8f);
    }
}

// ================= bf16 split kernels ==========================================
__global__ void split_kernel(const float* __restrict__ src,
                             __nv_bfloat16* __restrict__ hi,
                             __nv_bfloat16* __restrict__ lo, int n) {
    const int i = blockIdx.x * blockDim.x + threadIdx.x;
    if (i >= n) return;
    const float x = src[i];
    const __nv_bfloat16 h = __float2bfloat16(x);
    hi[i] = h;
    lo[i] = __float2bfloat16(x - __bfloat162float(h));
}

__global__ void split_w_kernel(const float* __restrict__ w0, const float* __restrict__ w1,
                               const float* __restrict__ w2, const float* __restrict__ w3,
                               const float* __restrict__ w4, const float* __restrict__ w5) {
    const int i = blockIdx.x * blockDim.x + threadIdx.x;
    if (i >= WTOT) return;
    float x;
    if      (i < 65536)  x = w0[i];
    else if (i < 131072) x = w1[i - 65536];
    else if (i < 196608) x = w2[i - 131072];
    else if (i < 262144) x = w3[i - 196608];
    else if (i < 327680) x = w4[i - 262144];
    else                 x = w5[i - 327680];
    const __nv_bfloat16 h = __float2bfloat16(x);
    g_wh[i] = h;
    g_wl[i] = __float2bfloat16(x - __bfloat162float(h));
}

// ================= HMMA GEMM: C = gelu(A1@W1^T [+ A2@W2^T] [+ bias]) ==========
// 3-term bf16 split (AhWh + AhWl + AlWh). CTA tile 128x128, 8 warps (2x4),
// per-warp 64x32 via 4x4 m16n8k16 frags. K staged in smem chunks of 32 with
// row stride 40 bf16 (conflict-free fragment loads).
#define SPAD 40
template <int NCOLS, bool DUAL, bool BIAS, bool SPLITOUT>
__global__ __launch_bounds__(256) void hmma_gemm_kernel(
    const __nv_bfloat16* __restrict__ a1h, const __nv_bfloat16* __restrict__ a1l,
    const __nv_bfloat16* __restrict__ w1h, const __nv_bfloat16* __restrict__ w1l,
    const __nv_bfloat16* __restrict__ a2h, const __nv_bfloat16* __restrict__ a2l,
    const __nv_bfloat16* __restrict__ w2h, const __nv_bfloat16* __restrict__ w2l,
    const float* __restrict__ bias, float* __restrict__ outF,
    __nv_bfloat16* __restrict__ outH, __nv_bfloat16* __restrict__ outL, int M) {
    __shared__ __nv_bfloat16 sAh[128 * SPAD], sAl[128 * SPAD];
    __shared__ __nv_bfloat16 sBh[128 * SPAD], sBl[128 * SPAD];

    const int tid  = threadIdx.x;
    const int wid  = tid >> 5;
    const int lane = tid & 31;
    const int gid  = lane >> 2;      // 0..7
    const int tig  = lane & 3;       // 0..3
    const int m0 = blockIdx.x * 128;
    const int n0 = blockIdx.y * 128;
    const int mw = (wid >> 2) * 64;  // warp m-offset within tile
    const int nw = (wid & 3) * 32;   // warp n-offset within tile

    float acc[4][4][4];
#pragma unroll
    for (int a = 0; a < 4; ++a)
#pragma unroll
        for (int b = 0; b < 4; ++b)
#pragma unroll
            for (int c = 0; c < 4; ++c) acc[a][b][c] = 0.0f;

    const int nsrc = DUAL ? 2 : 1;
    for (int src = 0; src < nsrc; ++src) {
        const __nv_bfloat16* Ah = (DUAL && src) ? a2h : a1h;
        const __nv_bfloat16* Al = (DUAL && src) ? a2l : a1l;
        const __nv_bfloat16* Wh = (DUAL && src) ? w2h : w1h;
        const __nv_bfloat16* Wl = (DUAL && src) ? w2l : w1l;

        for (int k0 = 0; k0 < HID; k0 += 32) {
            __syncthreads();
            // stage 128x32 tiles: 512 uint4 per tile, 256 threads -> 2 iters
#pragma unroll
            for (int u = tid; u < 512; u += 256) {
                const int r = u >> 2, qd = u & 3;
                const int mg = m0 + r;
                uint4 vh = make_uint4(0u, 0u, 0u, 0u), vl = vh;
                if (mg < M) {
                    vh = *reinterpret_cast<const uint4*>(Ah + (size_t)mg * HID + k0 + qd * 8);
                    vl = *reinterpret_cast<const uint4*>(Al + (size_t)mg * HID + k0 + qd * 8);
                }
                *reinterpret_cast<uint4*>(&sAh[r * SPAD + qd * 8]) = vh;
                *reinterpret_cast<uint4*>(&sAl[r * SPAD + qd * 8]) = vl;
                const uint4 bh = *reinterpret_cast<const uint4*>(Wh + (size_t)(n0 + r) * HID + k0 + qd * 8);
                const uint4 bl = *reinterpret_cast<const uint4*>(Wl + (size_t)(n0 + r) * HID + k0 + qd * 8);
                *reinterpret_cast<uint4*>(&sBh[r * SPAD + qd * 8]) = bh;
                *reinterpret_cast<uint4*>(&sBl[r * SPAD + qd * 8]) = bl;
            }
            __syncthreads();

#pragma unroll
            for (int kk = 0; kk < 32; kk += 16) {
                uint32_t afh[4][4], afl[4][4];
#pragma unroll
                for (int mi = 0; mi < 4; ++mi) {
                    const int base = (mw + 16 * mi + gid) * SPAD + kk + tig * 2;
                    afh[mi][0] = *reinterpret_cast<const uint32_t*>(&sAh[base]);
                    afh[mi][1] = *reinterpret_cast<const uint32_t*>(&sAh[base + 8 * SPAD]);
                    afh[mi][2] = *reinterpret_cast<const uint32_t*>(&sAh[base + 8]);
                    afh[mi][3] = *reinterpret_cast<const uint32_t*>(&sAh[base + 8 * SPAD + 8]);
                    afl[mi][0] = *reinterpret_cast<const uint32_t*>(&sAl[base]);
                    afl[mi][1] = *reinterpret_cast<const uint32_t*>(&sAl[base + 8 * SPAD]);
                    afl[mi][2] = *reinterpret_cast<const uint32_t*>(&sAl[base + 8]);
                    afl[mi][3] = *reinterpret_cast<const uint32_t*>(&sAl[base + 8 * SPAD + 8]);
                }
#pragma unroll
                for (int nj = 0; nj < 4; ++nj) {
                    const int bb = (nw + 8 * nj + gid) * SPAD + kk + tig * 2;
                    uint32_t bh[2], bl[2];
                    bh[0] = *reinterpret_cast<const uint32_t*>(&sBh[bb]);
                    bh[1] = *reinterpret_cast<const uint32_t*>(&sBh[bb + 8]);
                    bl[0] = *reinterpret_cast<const uint32_t*>(&sBl[bb]);
                    bl[1] = *reinterpret_cast<const uint32_t*>(&sBl[bb + 8]);
#pragma unroll
                    for (int mi = 0; mi < 4; ++mi) {
                        mma16816(acc[mi][nj], afh[mi], bh);
                        mma16816(acc[mi][nj], afh[mi], bl);
                        mma16816(acc[mi][nj], afl[mi], bh);
                    }
                }
            }
        }
    }

    // epilogue: bias + gelu (+ bf16 split)
#pragma unroll
    for (int mi = 0; mi < 4; ++mi) {
#pragma unroll
        for (int half = 0; half < 2; ++half) {
            const int m = m0 + mw + 16 * mi + gid + 8 * half;
            if (m >= M) continue;
#pragma unroll
            for (int nj = 0; nj < 4; ++nj) {
                const int ng = n0 + nw + 8 * nj + tig * 2;
                float v0 = acc[mi][nj][2 * half + 0];
                float v1 = acc[mi][nj][2 * half + 1];
                if (BIAS) { v0 += bias[ng]; v1 += bias[ng + 1]; }
                v0 = gelu_f(v0);
                v1 = gelu_f(v1);
                *reinterpret_cast<float2*>(outF + (size_t)m * NCOLS + ng) =
                    make_float2(v0, v1);
                if (SPLITOUT) {
                    const __nv_bfloat16 h0 = __float2bfloat16(v0);
                    const __nv_bfloat16 h1 = __float2bfloat16(v1);
                    outH[(size_t)m * 256 + ng]     = h0;
                    outH[(size_t)m * 256 + ng + 1] = h1;
                    outL[(size_t)m * 256 + ng]     = __float2bfloat16(v0 - __bfloat162float(h0));
                    outL[(size_t)m * 256 + ng + 1] = __float2bfloat16(v1 - __bfloat162float(h1));
                }
            }
        }
    }
}

// ================= neighbor aggregation (emits bf16 split) ====================
__global__ void agg_kernel(const float* __restrict__ h, const int* __restrict__ nidx,
                           const float* __restrict__ nw,
                           __nv_bfloat16* __restrict__ gh, __nv_bfloat16* __restrict__ gl) {
    const int n = blockIdx.x;
    const int d = threadIdx.x;
    __shared__ int   sidx[KNB];
    __shared__ float sw  [KNB];
    if (d < KNB) { sidx[d] = nidx[n * KNB + d]; sw[d] = nw[n * KNB + d]; }
    __syncthreads();
    float acc = 0.0f;
#pragma unroll
    for (int k = 0; k < KNB; ++k)
        acc = fmaf(sw[k], h[(size_t)sidx[k] * HID + d], acc);
    const __nv_bfloat16 hi = __float2bfloat16(acc);
    gh[(size_t)n * HID + d] = hi;
    gl[(size_t)n * HID + d] = __float2bfloat16(acc - __bfloat162float(hi));
}

// ================= layernorm + residual (emits fp32 + bf16 split) =============
__global__ void ln_res_kernel(const float* __restrict__ x, const float* __restrict__ g,
                              const float* __restrict__ b, float* __restrict__ h,
                              __nv_bfloat16* __restrict__ ah, __nv_bfloat16* __restrict__ al) {
    const int n = blockIdx.x;
    const int d = threadIdx.x;
    __shared__ float red[8];
    __shared__ float s_mu, s_rstd;

    const float v = x[(size_t)n * HID + d];
    float s = v;
#pragma unroll
    for (int o = 16; o > 0; o >>= 1) s += __shfl_xor_sync(0xffffffffu, s, o);
    if ((d & 31) == 0) red[d >> 5] = s;
    __syncthreads();
    if (d == 0) {
        float t = 0.0f;
        for (int i = 0; i < 8; ++i) t += red[i];
        s_mu = t * (1.0f / HID);
    }
    __syncthreads();
    const float mu = s_mu;
    const float df = v - mu;
    float q = df * df;
#pragma unroll
    for (int o = 16; o > 0; o >>= 1) q += __shfl_xor_sync(0xffffffffu, q, o);
    __syncthreads();
    if ((d & 31) == 0) red[d >> 5] = q;
    __syncthreads();
    if (d == 0) {
        float t = 0.0f;
        for (int i = 0; i < 8; ++i) t += red[i];
        s_rstd = rsqrtf(t * (1.0f / HID) + 1e-5f);
    }
    __syncthreads();
    const float hv = h[(size_t)n * HID + d] + df * s_rstd * g[d] + b[d];
    h[(size_t)n * HID + d] = hv;
    const __nv_bfloat16 hi = __float2bfloat16(hv);
    ah[(size_t)n * HID + d] = hi;
    al[(size_t)n * HID + d] = __float2bfloat16(hv - __bfloat162float(hi));
}

// ================= classifier layer 2 + sigmoid ================================
__global__ void cls2_kernel(const float* __restrict__ c1, const float* __restrict__ w2,
                            const float* __restrict__ b2, float* __restrict__ out, int M) {
    const int warp = threadIdx.x >> 5;
    const int lane = threadIdx.x & 31;
    const int r = blockIdx.x * 8 + warp;
    if (r >= M) return;
    float s = 0.0f;
#pragma unroll
    for (int j0 = 0; j0 < 128; j0 += 32)
        s = fmaf(c1[(size_t)r * 128 + j0 + lane], w2[j0 + lane], s);
#pragma unroll
    for (int o = 16; o > 0; o >>= 1) s += __shfl_xor_sync(0xffffffffu, s, o);
    if (lane == 0) {
        const float logit = s + b2[0];
        out[r] = 1.0f / (1.0f + expf(-logit));
    }
}

// ================= launch =======================================================
extern "C" void kernel_launch(void* const* d_in, const int* in_sizes, int n_in,
                              void* d_out, int out_size) {
    const float* feats  = (const float*)d_in[0];
    const float* cents  = (const float*)d_in[1];
    const float* enc_w  = (const float*)d_in[2];
    const float* enc_b  = (const float*)d_in[3];
    const float* g1_ws  = (const float*)d_in[4];
    const float* g1_wn  = (const float*)d_in[5];
    const float* g1_g   = (const float*)d_in[6];
    const float* g1_b   = (const float*)d_in[7];
    const float* g2_ws  = (const float*)d_in[8];
    const float* g2_wn  = (const float*)d_in[9];
    const float* g2_g   = (const float*)d_in[10];
    const float* g2_b   = (const float*)d_in[11];
    const float* cls_w1 = (const float*)d_in[12];
    const float* cls_b1 = (const float*)d_in[13];
    const float* cls_w2 = (const float*)d_in[14];
    const float* cls_b2 = (const float*)d_in[15];
    float* out = (float*)d_out;

    float *p_h, *p_tmp, *p_c1, *p_nw;
    int* p_nidx;
    __nv_bfloat16 *p_fh, *p_fl, *p_ah, *p_al, *p_gh, *p_gl, *p_wh, *p_wl;
    cudaGetSymbolAddress((void**)&p_h,    g_h);
    cudaGetSymbolAddress((void**)&p_tmp,  g_tmp);
    cudaGetSymbolAddress((void**)&p_c1,   g_c1);
    cudaGetSymbolAddress((void**)&p_nidx, g_nidx);
    cudaGetSymbolAddress((void**)&p_nw,   g_nw);
    cudaGetSymbolAddress((void**)&p_fh,   g_fh);
    cudaGetSymbolAddress((void**)&p_fl,   g_fl);
    cudaGetSymbolAddress((void**)&p_ah,   g_ah);
    cudaGetSymbolAddress((void**)&p_al,   g_al);
    cudaGetSymbolAddress((void**)&p_gh,   g_gh);
    cudaGetSymbolAddress((void**)&p_gl,   g_gl);
    cudaGetSymbolAddress((void**)&p_wh,   g_wh);
    cudaGetSymbolAddress((void**)&p_wl,   g_wl);

    const int M = NPTS;
    const int NBLK = (M + 127) / 128;   // 94
    const dim3 gFull(NBLK, 2);          // 128x128 tiles over N=256
    const dim3 gHalf(NBLK, 1);          // N=128

    // ---- grid-KNN build + query ----
    knn_init_kernel   <<<(NCELL + 256) / 256, 256>>>();
    knn_bbox_kernel   <<<(NPTS + 255) / 256, 256>>>(cents);
    knn_count_kernel  <<<(NPTS + 255) / 256, 256>>>(cents);
    knn_scan_kernel   <<<1, 256>>>();
    knn_scatter_kernel<<<(NPTS + 255) / 256, 256>>>(cents);
    knn_query_kernel  <<<(NPTS * 32 + 255) / 256, 256>>>(p_nidx, p_nw);

    // ---- operand splits ----
    split_w_kernel<<<(WTOT + 255) / 256, 256>>>(enc_w, g1_ws, g1_wn, g2_ws, g2_wn, cls_w1);
    split_kernel<<<(NPTS * HID + 255) / 256, 256>>>(feats, p_fh, p_fl, NPTS * HID);

    // encoder: h = gelu(feats @ enc_w^T + enc_b), emits split(h)
    hmma_gemm_kernel<256, false, true, true><<<gFull, 256>>>(
        p_fh, p_fl, p_wh + 0, p_wl + 0,
        nullptr, nullptr, nullptr, nullptr,
        enc_b, p_h, p_ah, p_al, M);

    // SAGE layer 1
    agg_kernel<<<NPTS, HID>>>(p_h, p_nidx, p_nw, p_gh, p_gl);
    hmma_gemm_kernel<256, true, false, false><<<gFull, 256>>>(
        p_ah, p_al, p_wh + 65536, p_wl + 65536,
        p_gh, p_gl, p_wh + 131072, p_wl + 131072,
        nullptr, p_tmp, nullptr, nullptr, M);
    ln_res_kernel<<<NPTS, HID>>>(p_tmp, g1_g, g1_b, p_h, p_ah, p_al);

    // SAGE layer 2
    agg_kernel<<<NPTS, HID>>>(p_h, p_nidx, p_nw, p_gh, p_gl);
    hmma_gemm_kernel<256, true, false, false><<<gFull, 256>>>(
        p_ah, p_al, p_wh + 196608, p_wl + 196608,
        p_gh, p_gl, p_wh + 262144, p_wl + 262144,
        nullptr, p_tmp, nullptr, nullptr, M);
    ln_res_kernel<<<NPTS, HID>>>(p_tmp, g2_g, g2_b, p_h, p_ah, p_al);

    // classifier
    hmma_gemm_kernel<128, false, true, false><<<gHalf, 256>>>(
        p_ah, p_al, p_wh + 327680, p_wl + 327680,
        nullptr, nullptr, nullptr, nullptr,
        cls_b1, p_c1, nullptr, nullptr, M);
    cls2_kernel<<<(M + 7) / 8, 256>>>(p_c1, cls_w2, cls_b2, out, M);
}

// round 7
// speedup vs baseline: 3.7355x; 1.2489x over previous
#include <cuda_runtime.h>
#include <cuda_bf16.h>
#include <cstdint>
#include <cfloat>
#include <math.h>

#define NPTS 12000
#define MPAD 12032
#define HID  256
#define KNB  16
#define G    64
#define NCELL (G * G)

// ---------------- scratch (allocation-free: __device__ globals) --------------
__device__ float g_h   [NPTS * HID];
__device__ float g_tmp [NPTS * HID];
__device__ float g_c1  [NPTS * (HID / 2)];
__device__ int   g_nidx[NPTS * KNB];
__device__ float g_nw  [NPTS * KNB];

// bf16 split operand buffers (padded rows so tail-tile cp.async stays in-bounds)
__device__ __nv_bfloat16 g_ah[MPAD * HID], g_al[MPAD * HID];   // h split
__device__ __nv_bfloat16 g_gh[MPAD * HID], g_gl[MPAD * HID];   // agg split
#define WTOT 360448
__device__ __nv_bfloat16 g_wh[WTOT], g_wl[WTOT];
// slots: enc=0, g1ws=65536, g1wn=131072, g2ws=196608, g2wn=262144, cls=327680

// grid-knn scratch
__device__ unsigned int g_bbox[4];
__device__ int    g_cellcnt [NCELL + 1];
__device__ int    g_cellstart[NCELL + 1];
__device__ float2 g_pts [NPTS];
__device__ int    g_sidx[NPTS];

__device__ __forceinline__ float gelu_f(float x) {
    return 0.5f * x * (1.0f + erff(x * 0.70710678118654752440f));
}

__device__ __forceinline__ unsigned int fenc(float f) {
    unsigned int u = __float_as_uint(f);
    return (u & 0x80000000u) ? ~u : (u | 0x80000000u);
}
__device__ __forceinline__ float fdec(unsigned int u) {
    return __uint_as_float((u & 0x80000000u) ? (u ^ 0x80000000u) : ~u);
}

__device__ __forceinline__ uint32_t smem_u32(const void* p) {
    uint32_t a;
    asm("{ .reg .u64 t; cvta.to.shared.u64 t, %1; cvt.u32.u64 %0, t; }" : "=r"(a) : "l"(p));
    return a;
}
__device__ __forceinline__ void cpa16(__nv_bfloat16* dst, const __nv_bfloat16* src) {
    const uint32_t d = smem_u32(dst);
    asm volatile("cp.async.cg.shared.global [%0], [%1], 16;" :: "r"(d), "l"(src) : "memory");
}

// HMMA: D(f32) += A(bf16,row) * B(bf16,col), m16n8k16
__device__ __forceinline__ void mma16816(float* c, const uint32_t* a, const uint32_t* b) {
    asm volatile(
        "mma.sync.aligned.m16n8k16.row.col.f32.bf16.bf16.f32 "
        "{%0,%1,%2,%3}, {%4,%5,%6,%7}, {%8,%9}, {%0,%1,%2,%3};"
        : "+f"(c[0]), "+f"(c[1]), "+f"(c[2]), "+f"(c[3])
        : "r"(a[0]), "r"(a[1]), "r"(a[2]), "r"(a[3]), "r"(b[0]), "r"(b[1]));
}

// ================= KNN ========================================================
__global__ void knn_init_kernel() {
    const int t = blockIdx.x * blockDim.x + threadIdx.x;
    if (t <= NCELL) { g_cellcnt[t] = 0; }
    if (t == 0) {
        g_bbox[0] = 0xFFFFFFFFu; g_bbox[1] = 0u;
        g_bbox[2] = 0xFFFFFFFFu; g_bbox[3] = 0u;
    }
}

__global__ void knn_bbox_kernel(const float* __restrict__ cents) {
    const int i = blockIdx.x * blockDim.x + threadIdx.x;
    if (i >= NPTS) return;
    const float x = cents[2 * i], y = cents[2 * i + 1];
    atomicMin(&g_bbox[0], fenc(x));
    atomicMax(&g_bbox[1], fenc(x));
    atomicMin(&g_bbox[2], fenc(y));
    atomicMax(&g_bbox[3], fenc(y));
}

__device__ __forceinline__ void grid_params(float& xmin, float& ymin,
                                            float& iwx, float& iwy,
                                            float& wx, float& wy) {
    xmin = fdec(g_bbox[0]);
    const float xmax = fdec(g_bbox[1]);
    ymin = fdec(g_bbox[2]);
    const float ymax = fdec(g_bbox[3]);
    const float rx = fmaxf(xmax - xmin, 1e-20f);
    const float ry = fmaxf(ymax - ymin, 1e-20f);
    iwx = (float)G / rx; iwy = (float)G / ry;
    wx = rx / (float)G;  wy = ry / (float)G;
}

__device__ __forceinline__ int cell_x(float x, float xmin, float iwx) {
    int c = (int)((x - xmin) * iwx);
    return min(max(c, 0), G - 1);
}

__global__ void knn_count_kernel(const float* __restrict__ cents) {
    const int i = blockIdx.x * blockDim.x + threadIdx.x;
    if (i >= NPTS) return;
    float xmin, ymin, iwx, iwy, wx, wy;
    grid_params(xmin, ymin, iwx, iwy, wx, wy);
    const int cx = cell_x(cents[2 * i],     xmin, iwx);
    const int cy = cell_x(cents[2 * i + 1], ymin, iwy);
    atomicAdd(&g_cellcnt[cy * G + cx], 1);
}

__global__ void knn_scan_kernel() {
    __shared__ int wsum[8];
    const int t = threadIdx.x;
    const int lane = t & 31;
    const int warp = t >> 5;
    const int base = t * 16;
    int c16[16];
#pragma unroll
    for (int q = 0; q < 4; ++q)
        *reinterpret_cast<int4*>(&c16[q * 4]) =
            *reinterpret_cast<const int4*>(&g_cellcnt[base + q * 4]);
    int loc[16];
    int s = 0;
#pragma unroll
    for (int j = 0; j < 16; ++j) { loc[j] = s; s += c16[j]; }
    int v = s;
#pragma unroll
    for (int off = 1; off < 32; off <<= 1) {
        const int n = __shfl_up_sync(0xffffffffu, v, off);
        if (lane >= off) v += n;
    }
    if (lane == 31) wsum[warp] = v;
    __syncthreads();
    if (t == 0) {
        int run = 0;
        for (int i = 0; i < 8; ++i) { const int tmp = wsum[i]; wsum[i] = run; run += tmp; }
    }
    __syncthreads();
    const int pre = wsum[warp] + (v - s);
#pragma unroll
    for (int j = 0; j < 16; ++j) loc[j] += pre;
#pragma unroll
    for (int q = 0; q < 4; ++q) {
        *reinterpret_cast<int4*>(&g_cellstart[base + q * 4]) =
            *reinterpret_cast<const int4*>(&loc[q * 4]);
        *reinterpret_cast<int4*>(&g_cellcnt[base + q * 4]) =
            *reinterpret_cast<const int4*>(&loc[q * 4]);
    }
    if (t == 255) g_cellstart[NCELL] = NPTS;
}

__global__ void knn_scatter_kernel(const float* __restrict__ cents) {
    const int i = blockIdx.x * blockDim.x + threadIdx.x;
    if (i >= NPTS) return;
    float xmin, ymin, iwx, iwy, wx, wy;
    grid_params(xmin, ymin, iwx, iwy, wx, wy);
    const float x = cents[2 * i], y = cents[2 * i + 1];
    const int cx = cell_x(x, xmin, iwx);
    const int cy = cell_x(y, ymin, iwy);
    const int slot = atomicAdd(&g_cellcnt[cy * G + cx], 1);
    g_pts [slot] = make_float2(x, y);
    g_sidx[slot] = i;
}

__global__ void knn_query_kernel(int* __restrict__ nidx, float* __restrict__ nw) {
    const int w = (blockIdx.x * blockDim.x + threadIdx.x) >> 5;
    const int lane = threadIdx.x & 31;
    if (w >= NPTS) return;
    const int s = w;
    const float2 q = g_pts[s];
    const int i = g_sidx[s];

    float xmin, ymin, iwx, iwy, wx, wy;
    grid_params(xmin, ymin, iwx, iwy, wx, wy);
    const int cx = cell_x(q.x, xmin, iwx);
    const int cy = cell_x(q.y, ymin, iwy);

    float vals[KNB];
    int   ids [KNB];
#pragma unroll
    for (int t = 0; t < KNB; ++t) { vals[t] = FLT_MAX; ids[t] = 0; }
    float maxv = FLT_MAX;
    int   maxslot = 0;

    for (int r = 0; r < G; ++r) {
        const int ylo = max(cy - r, 0), yhi = min(cy + r, G - 1);
        for (int vy = ylo; vy <= yhi; ++vy) {
            const bool edge_row = (vy == cy - r) || (vy == cy + r);
            int ps0 = 0, pe0 = 0, ps1 = 0, pe1 = 0;
            if (edge_row) {
                const int xl = max(cx - r, 0), xh = min(cx + r, G - 1);
                ps0 = g_cellstart[vy * G + xl];
                pe0 = g_cellstart[vy * G + xh + 1];
            } else {
                if (cx - r >= 0) {
                    ps0 = g_cellstart[vy * G + cx - r];
                    pe0 = g_cellstart[vy * G + cx - r + 1];
                }
                if (cx + r <= G - 1) {
                    ps1 = g_cellstart[vy * G + cx + r];
                    pe1 = g_cellstart[vy * G + cx + r + 1];
                }
            }
#pragma unroll
            for (int seg = 0; seg < 2; ++seg) {
                const int ps = seg ? ps1 : ps0;
                const int pe = seg ? pe1 : pe0;
                for (int p0 = ps; p0 < pe; p0 += 32) {
                    const int p = p0 + lane;
                    float d2 = FLT_MAX;
                    if (p < pe && p != s) {
                        const float2 f = g_pts[p];
                        const float dx = q.x - f.x;
                        const float dy = q.y - f.y;
                        d2 = fmaf(dx, dx, dy * dy);
                    }
                    unsigned int m = __ballot_sync(0xffffffffu, d2 < maxv);
                    while (m) {
                        const int l = __ffs(m) - 1;
                        m &= m - 1;
                        const float dd = __shfl_sync(0xffffffffu, d2, l);
                        if (dd < maxv) {
                            const int pp = __shfl_sync(0xffffffffu, p, l);
#pragma unroll
                            for (int t = 0; t < KNB; ++t)
                                if (t == maxslot) { vals[t] = dd; ids[t] = pp; }
                            maxv = vals[0]; maxslot = 0;
#pragma unroll
                            for (int t = 1; t < KNB; ++t)
                                if (vals[t] > maxv) { maxv = vals[t]; maxslot = t; }
                        }
                    }
                }
            }
        }
        if (maxv < FLT_MAX) {
            const float bl = (cx - r > 0)     ? q.x - (xmin + (float)(cx - r) * wx)     : FLT_MAX;
            const float br = (cx + r < G - 1) ? (xmin + (float)(cx + r + 1) * wx) - q.x : FLT_MAX;
            const float bb = (cy - r > 0)     ? q.y - (ymin + (float)(cy - r) * wy)     : FLT_MAX;
            const float bt = (cy + r < G - 1) ? (ymin + (float)(cy + r + 1) * wy) - q.y : FLT_MAX;
            const float b = fminf(fminf(bl, br), fminf(bb, bt));
            if (b == FLT_MAX || (b > 0.0f && b * b > maxv)) break;
        }
    }

    int myslot = 0;
#pragma unroll
    for (int t = 0; t < KNB; ++t)
        if (t == lane) myslot = ids[t];

    float invd = 0.0f;
    int oid = 0;
    if (lane < KNB) {
        const float2 f = g_pts[myslot];
        oid = g_sidx[myslot];
        const float xi = q.x, yi = q.y;
        const float sqi = __fadd_rn(__fmul_rn(xi, xi), __fmul_rn(yi, yi));
        const float sqj = __fadd_rn(__fmul_rn(f.x, f.x), __fmul_rn(f.y, f.y));
        const float dot = __fadd_rn(__fmul_rn(xi, f.x), __fmul_rn(yi, f.y));
        const float d2  = __fsub_rn(__fadd_rn(sqi, sqj), __fmul_rn(2.0f, dot));
        const float dist = sqrtf(fmaxf(d2, 0.0f));
        invd = 1.0f / fmaxf(dist, 1e-4f);
    }
    float tot = invd;
#pragma unroll
    for (int o = 16; o > 0; o >>= 1)
        tot += __shfl_xor_sync(0xffffffffu, tot, o);
    if (lane < KNB) {
        nidx[i * KNB + lane] = oid;
        nw  [i * KNB + lane] = invd / fmaxf(tot, 1e-8f);
    }
}

// ================= weight split ================================================
__global__ void split_w_kernel(const float* __restrict__ w0, const float* __restrict__ w1,
                               const float* __restrict__ w2, const float* __restrict__ w3,
                               const float* __restrict__ w4, const float* __restrict__ w5) {
    const int i = blockIdx.x * blockDim.x + threadIdx.x;
    if (i >= WTOT) return;
    float x;
    if      (i < 65536)  x = w0[i];
    else if (i < 131072) x = w1[i - 65536];
    else if (i < 196608) x = w2[i - 131072];
    else if (i < 262144) x = w3[i - 196608];
    else if (i < 327680) x = w4[i - 262144];
    else                 x = w5[i - 327680];
    const __nv_bfloat16 h = __float2bfloat16(x);
    g_wh[i] = h;
    g_wl[i] = __float2bfloat16(x - __bfloat162float(h));
}

// ================= HMMA GEMM, cp.async double-buffered ========================
// 3-term bf16 split (AhWh + AhWl + AlWh). CTA tile 128x128, 8 warps (2x4),
// per-warp 64x32 via 4x4 m16n8k16 frags. K-chunks of 32, 2-stage pipeline.
#define SPAD 40
#define STILE (128 * SPAD)
template <int NCOLS, bool DUAL, bool BIAS, bool SPLITOUT, bool CONVA>
__global__ __launch_bounds__(256) void hmma_gemm_kernel(
    const __nv_bfloat16* __restrict__ a1h, const __nv_bfloat16* __restrict__ a1l,
    const float* __restrict__ a1f,
    const __nv_bfloat16* __restrict__ w1h, const __nv_bfloat16* __restrict__ w1l,
    const __nv_bfloat16* __restrict__ a2h, const __nv_bfloat16* __restrict__ a2l,
    const __nv_bfloat16* __restrict__ w2h, const __nv_bfloat16* __restrict__ w2l,
    const float* __restrict__ bias, float* __restrict__ outF,
    __nv_bfloat16* __restrict__ outH, __nv_bfloat16* __restrict__ outL, int M) {
    extern __shared__ __nv_bfloat16 smem[];

    const int tid  = threadIdx.x;
    const int wid  = tid >> 5;
    const int lane = tid & 31;
    const int gid  = lane >> 2;
    const int tig  = lane & 3;
    const int m0 = blockIdx.x * 128;
    const int n0 = blockIdx.y * 128;
    const int mw = (wid >> 2) * 64;
    const int nw = (wid & 3) * 32;
    const int nchunks = DUAL ? 16 : 8;

    float acc[4][4][4];
#pragma unroll
    for (int a = 0; a < 4; ++a)
#pragma unroll
        for (int b = 0; b < 4; ++b)
#pragma unroll
            for (int c = 0; c < 4; ++c) acc[a][b][c] = 0.0f;

    // ---- staging: issue cp.async (and manual conv for CONVA) for chunk c ----
    auto stage = [&](int c) {
        const int k0 = (c & 7) * 32;
        const bool s1 = DUAL && (c >= 8);
        const __nv_bfloat16* Ah = s1 ? a2h : a1h;
        const __nv_bfloat16* Al = s1 ? a2l : a1l;
        const __nv_bfloat16* Wh = s1 ? w2h : w1h;
        const __nv_bfloat16* Wl = s1 ? w2l : w1l;
        __nv_bfloat16* buf = smem + (c & 1) * 4 * STILE;
        __nv_bfloat16* bAh = buf;
        __nv_bfloat16* bAl = buf + STILE;
        __nv_bfloat16* bBh = buf + 2 * STILE;
        __nv_bfloat16* bBl = buf + 3 * STILE;
#pragma unroll
        for (int u = tid; u < 512; u += 256) {
            const int r = u >> 2, qd = u & 3;
            const int off = r * SPAD + qd * 8;
            cpa16(bBh + off, Wh + (size_t)(n0 + r) * HID + k0 + qd * 8);
            cpa16(bBl + off, Wl + (size_t)(n0 + r) * HID + k0 + qd * 8);
            if (CONVA) {
                const int mg = m0 + r;
                __align__(16) __nv_bfloat16 hh[8], ll[8];
                if (mg < M) {
                    const float* fp = a1f + (size_t)mg * HID + k0 + qd * 8;
                    const float4 f0 = *reinterpret_cast<const float4*>(fp);
                    const float4 f1 = *reinterpret_cast<const float4*>(fp + 4);
                    const float fv[8] = {f0.x, f0.y, f0.z, f0.w, f1.x, f1.y, f1.z, f1.w};
#pragma unroll
                    for (int j = 0; j < 8; ++j) {
                        hh[j] = __float2bfloat16(fv[j]);
                        ll[j] = __float2bfloat16(fv[j] - __bfloat162float(hh[j]));
                    }
                } else {
#pragma unroll
                    for (int j = 0; j < 8; ++j) { hh[j] = __nv_bfloat16(0.f); ll[j] = __nv_bfloat16(0.f); }
                }
                *reinterpret_cast<uint4*>(bAh + off) = *reinterpret_cast<const uint4*>(hh);
                *reinterpret_cast<uint4*>(bAl + off) = *reinterpret_cast<const uint4*>(ll);
            } else {
                // A buffers padded to MPAD rows: tail over-read is in-bounds
                cpa16(bAh + off, Ah + (size_t)(m0 + r) * HID + k0 + qd * 8);
                cpa16(bAl + off, Al + (size_t)(m0 + r) * HID + k0 + qd * 8);
            }
        }
        asm volatile("cp.async.commit_group;" ::: "memory");
    };

    stage(0);
    for (int c = 0; c < nchunks; ++c) {
        if (c + 1 < nchunks) {
            stage(c + 1);
            asm volatile("cp.async.wait_group 1;" ::: "memory");
        } else {
            asm volatile("cp.async.wait_group 0;" ::: "memory");
        }
        __syncthreads();

        const __nv_bfloat16* buf = smem + (c & 1) * 4 * STILE;
        const __nv_bfloat16* sAh = buf;
        const __nv_bfloat16* sAl = buf + STILE;
        const __nv_bfloat16* sBh = buf + 2 * STILE;
        const __nv_bfloat16* sBl = buf + 3 * STILE;

#pragma unroll
        for (int kk = 0; kk < 32; kk += 16) {
            uint32_t afh[4][4], afl[4][4];
#pragma unroll
            for (int mi = 0; mi < 4; ++mi) {
                const int base = (mw + 16 * mi + gid) * SPAD + kk + tig * 2;
                afh[mi][0] = *reinterpret_cast<const uint32_t*>(&sAh[base]);
                afh[mi][1] = *reinterpret_cast<const uint32_t*>(&sAh[base + 8 * SPAD]);
                afh[mi][2] = *reinterpret_cast<const uint32_t*>(&sAh[base + 8]);
                afh[mi][3] = *reinterpret_cast<const uint32_t*>(&sAh[base + 8 * SPAD + 8]);
                afl[mi][0] = *reinterpret_cast<const uint32_t*>(&sAl[base]);
                afl[mi][1] = *reinterpret_cast<const uint32_t*>(&sAl[base + 8 * SPAD]);
                afl[mi][2] = *reinterpret_cast<const uint32_t*>(&sAl[base + 8]);
                afl[mi][3] = *reinterpret_cast<const uint32_t*>(&sAl[base + 8 * SPAD + 8]);
            }
#pragma unroll
            for (int nj = 0; nj < 4; ++nj) {
                const int bb = (nw + 8 * nj + gid) * SPAD + kk + tig * 2;
                uint32_t bh[2], bl[2];
                bh[0] = *reinterpret_cast<const uint32_t*>(&sBh[bb]);
                bh[1] = *reinterpret_cast<const uint32_t*>(&sBh[bb + 8]);
                bl[0] = *reinterpret_cast<const uint32_t*>(&sBl[bb]);
                bl[1] = *reinterpret_cast<const uint32_t*>(&sBl[bb + 8]);
#pragma unroll
                for (int mi = 0; mi < 4; ++mi) {
                    mma16816(acc[mi][nj], afh[mi], bh);
                    mma16816(acc[mi][nj], afh[mi], bl);
                    mma16816(acc[mi][nj], afl[mi], bh);
                }
            }
        }
        __syncthreads();
    }

    // epilogue: bias + gelu (+ bf16 split)
#pragma unroll
    for (int mi = 0; mi < 4; ++mi) {
#pragma unroll
        for (int half = 0; half < 2; ++half) {
            const int m = m0 + mw + 16 * mi + gid + 8 * half;
            if (m >= M) continue;
#pragma unroll
            for (int nj = 0; nj < 4; ++nj) {
                const int ng = n0 + nw + 8 * nj + tig * 2;
                float v0 = acc[mi][nj][2 * half + 0];
                float v1 = acc[mi][nj][2 * half + 1];
                if (BIAS) { v0 += bias[ng]; v1 += bias[ng + 1]; }
                v0 = gelu_f(v0);
                v1 = gelu_f(v1);
                *reinterpret_cast<float2*>(outF + (size_t)m * NCOLS + ng) =
                    make_float2(v0, v1);
                if (SPLITOUT) {
                    const __nv_bfloat16 h0 = __float2bfloat16(v0);
                    const __nv_bfloat16 h1 = __float2bfloat16(v1);
                    outH[(size_t)m * 256 + ng]     = h0;
                    outH[(size_t)m * 256 + ng + 1] = h1;
                    outL[(size_t)m * 256 + ng]     = __float2bfloat16(v0 - __bfloat162float(h0));
                    outL[(size_t)m * 256 + ng + 1] = __float2bfloat16(v1 - __bfloat162float(h1));
                }
            }
        }
    }
}

// ================= neighbor aggregation (emits bf16 split) ====================
__global__ void agg_kernel(const float* __restrict__ h, const int* __restrict__ nidx,
                           const float* __restrict__ nw,
                           __nv_bfloat16* __restrict__ gh, __nv_bfloat16* __restrict__ gl) {
    const int n = blockIdx.x;
    const int d = threadIdx.x;
    __shared__ int   sidx[KNB];
    __shared__ float sw  [KNB];
    if (d < KNB) { sidx[d] = nidx[n * KNB + d]; sw[d] = nw[n * KNB + d]; }
    __syncthreads();
    float acc = 0.0f;
#pragma unroll
    for (int k = 0; k < KNB; ++k)
        acc = fmaf(sw[k], h[(size_t)sidx[k] * HID + d], acc);
    const __nv_bfloat16 hi = __float2bfloat16(acc);
    gh[(size_t)n * HID + d] = hi;
    gl[(size_t)n * HID + d] = __float2bfloat16(acc - __bfloat162float(hi));
}

// ================= layernorm + residual (emits fp32 + bf16 split) =============
__global__ void ln_res_kernel(const float* __restrict__ x, const float* __restrict__ g,
                              const float* __restrict__ b, float* __restrict__ h,
                              __nv_bfloat16* __restrict__ ah, __nv_bfloat16* __restrict__ al) {
    const int n = blockIdx.x;
    const int d = threadIdx.x;
    __shared__ float red[8];
    __shared__ float s_mu, s_rstd;

    const float v = x[(size_t)n * HID + d];
    float s = v;
#pragma unroll
    for (int o = 16; o > 0; o >>= 1) s += __shfl_xor_sync(0xffffffffu, s, o);
    if ((d & 31) == 0) red[d >> 5] = s;
    __syncthreads();
    if (d == 0) {
        float t = 0.0f;
        for (int i = 0; i < 8; ++i) t += red[i];
        s_mu = t * (1.0f / HID);
    }
    __syncthreads();
    const float mu = s_mu;
    const float df = v - mu;
    float q = df * df;
#pragma unroll
    for (int o = 16; o > 0; o >>= 1) q += __shfl_xor_sync(0xffffffffu, q, o);
    __syncthreads();
    if ((d & 31) == 0) red[d >> 5] = q;
    __syncthreads();
    if (d == 0) {
        float t = 0.0f;
        for (int i = 0; i < 8; ++i) t += red[i];
        s_rstd = rsqrtf(t * (1.0f / HID) + 1e-5f);
    }
    __syncthreads();
    const float hv = h[(size_t)n * HID + d] + df * s_rstd * g[d] + b[d];
    h[(size_t)n * HID + d] = hv;
    const __nv_bfloat16 hi = __float2bfloat16(hv);
    ah[(size_t)n * HID + d] = hi;
    al[(size_t)n * HID + d] = __float2bfloat16(hv - __bfloat162float(hi));
}

// ================= classifier layer 2 + sigmoid ================================
__global__ void cls2_kernel(const float* __restrict__ c1, const float* __restrict__ w2,
                            const float* __restrict__ b2, float* __restrict__ out, int M) {
    const int warp = threadIdx.x >> 5;
    const int lane = threadIdx.x & 31;
    const int r = blockIdx.x * 8 + warp;
    if (r >= M) return;
    float s = 0.0f;
#pragma unroll
    for (int j0 = 0; j0 < 128; j0 += 32)
        s = fmaf(c1[(size_t)r * 128 + j0 + lane], w2[j0 + lane], s);
#pragma unroll
    for (int o = 16; o > 0; o >>= 1) s += __shfl_xor_sync(0xffffffffu, s, o);
    if (lane == 0) {
        const float logit = s + b2[0];
        out[r] = 1.0f / (1.0f + expf(-logit));
    }
}

// ================= launch =======================================================
extern "C" void kernel_launch(void* const* d_in, const int* in_sizes, int n_in,
                              void* d_out, int out_size) {
    const float* feats  = (const float*)d_in[0];
    const float* cents  = (const float*)d_in[1];
    const float* enc_w  = (const float*)d_in[2];
    const float* enc_b  = (const float*)d_in[3];
    const float* g1_ws  = (const float*)d_in[4];
    const float* g1_wn  = (const float*)d_in[5];
    const float* g1_g   = (const float*)d_in[6];
    const float* g1_b   = (const float*)d_in[7];
    const float* g2_ws  = (const float*)d_in[8];
    const float* g2_wn  = (const float*)d_in[9];
    const float* g2_g   = (const float*)d_in[10];
    const float* g2_b   = (const float*)d_in[11];
    const float* cls_w1 = (const float*)d_in[12];
    const float* cls_b1 = (const float*)d_in[13];
    const float* cls_w2 = (const float*)d_in[14];
    const float* cls_b2 = (const float*)d_in[15];
    float* out = (float*)d_out;

    float *p_h, *p_tmp, *p_c1, *p_nw;
    int* p_nidx;
    __nv_bfloat16 *p_ah, *p_al, *p_gh, *p_gl, *p_wh, *p_wl;
    cudaGetSymbolAddress((void**)&p_h,    g_h);
    cudaGetSymbolAddress((void**)&p_tmp,  g_tmp);
    cudaGetSymbolAddress((void**)&p_c1,   g_c1);
    cudaGetSymbolAddress((void**)&p_nidx, g_nidx);
    cudaGetSymbolAddress((void**)&p_nw,   g_nw);
    cudaGetSymbolAddress((void**)&p_ah,   g_ah);
    cudaGetSymbolAddress((void**)&p_al,   g_al);
    cudaGetSymbolAddress((void**)&p_gh,   g_gh);
    cudaGetSymbolAddress((void**)&p_gl,   g_gl);
    cudaGetSymbolAddress((void**)&p_wh,   g_wh);
    cudaGetSymbolAddress((void**)&p_wl,   g_wl);

    const int M = NPTS;
    const int NBLK = (M + 127) / 128;   // 94
    const dim3 gFull(NBLK, 2);
    const dim3 gHalf(NBLK, 1);
    const int SMEM_DYN = 2 * 4 * STILE * (int)sizeof(__nv_bfloat16);  // 81920

    cudaFuncSetAttribute(hmma_gemm_kernel<256, false, true,  true,  true >,
                         cudaFuncAttributeMaxDynamicSharedMemorySize, SMEM_DYN);
    cudaFuncSetAttribute(hmma_gemm_kernel<256, true,  false, false, false>,
                         cudaFuncAttributeMaxDynamicSharedMemorySize, SMEM_DYN);
    cudaFuncSetAttribute(hmma_gemm_kernel<128, false, true,  false, false>,
                         cudaFuncAttributeMaxDynamicSharedMemorySize, SMEM_DYN);

    // ---- fork: KNN chain on s2, splits+encoder on main stream ----
    cudaStream_t s2;
    cudaStreamCreateWithFlags(&s2, cudaStreamNonBlocking);
    cudaEvent_t evF, evJ;
    cudaEventCreateWithFlags(&evF, cudaEventDisableTiming);
    cudaEventCreateWithFlags(&evJ, cudaEventDisableTiming);
    cudaEventRecord(evF, 0);
    cudaStreamWaitEvent(s2, evF, 0);

    knn_init_kernel   <<<(NCELL + 256) / 256, 256, 0, s2>>>();
    knn_bbox_kernel   <<<(NPTS + 255) / 256, 256, 0, s2>>>(cents);
    knn_count_kernel  <<<(NPTS + 255) / 256, 256, 0, s2>>>(cents);
    knn_scan_kernel   <<<1, 256, 0, s2>>>();
    knn_scatter_kernel<<<(NPTS + 255) / 256, 256, 0, s2>>>(cents);
    knn_query_kernel  <<<(NPTS * 32 + 255) / 256, 256, 0, s2>>>(p_nidx, p_nw);
    cudaEventRecord(evJ, s2);

    // main stream: weight splits + encoder (feats converted in-kernel)
    split_w_kernel<<<(WTOT + 255) / 256, 256>>>(enc_w, g1_ws, g1_wn, g2_ws, g2_wn, cls_w1);
    hmma_gemm_kernel<256, false, true, true, true><<<gFull, 256, SMEM_DYN>>>(
        nullptr, nullptr, feats, p_wh + 0, p_wl + 0,
        nullptr, nullptr, nullptr, nullptr,
        enc_b, p_h, p_ah, p_al, M);

    // join: agg needs both h and the knn graph
    cudaStreamWaitEvent(0, evJ, 0);

    // SAGE layer 1
    agg_kernel<<<NPTS, HID>>>(p_h, p_nidx, p_nw, p_gh, p_gl);
    hmma_gemm_kernel<256, true, false, false, false><<<gFull, 256, SMEM_DYN>>>(
        p_ah, p_al, nullptr, p_wh + 65536, p_wl + 65536,
        p_gh, p_gl, p_wh + 131072, p_wl + 131072,
        nullptr, p_tmp, nullptr, nullptr, M);
    ln_res_kernel<<<NPTS, HID>>>(p_tmp, g1_g, g1_b, p_h, p_ah, p_al);

    // SAGE layer 2
    agg_kernel<<<NPTS, HID>>>(p_h, p_nidx, p_nw, p_gh, p_gl);
    hmma_gemm_kernel<256, true, false, false, false><<<gFull, 256, SMEM_DYN>>>(
        p_ah, p_al, nullptr, p_wh + 196608, p_wl + 196608,
        p_gh, p_gl, p_wh + 262144, p_wl + 262144,
        nullptr, p_tmp, nullptr, nullptr, M);
    ln_res_kernel<<<NPTS, HID>>>(p_tmp, g2_g, g2_b, p_h, p_ah, p_al);

    // classifier
    hmma_gemm_kernel<128, false, true, false, false><<<gHalf, 256, SMEM_DYN>>>(
        p_ah, p_al, nullptr, p_wh + 327680, p_wl + 327680,
        nullptr, nullptr, nullptr, nullptr,
        cls_b1, p_c1, nullptr, nullptr, M);
    cls2_kernel<<<(M + 7) / 8, 256>>>(p_c1, cls_w2, cls_b2, out, M);
}

// round 8
// speedup vs baseline: 3.7886x; 1.0142x over previous
#include <cuda_runtime.h>
#include <cuda_bf16.h>
#include <cstdint>
#include <cfloat>
#include <math.h>

#define NPTS 12000
#define MPAD 12032
#define HID  256
#define KNB  16
#define G    64
#define NCELL (G * G)

// ---------------- scratch (allocation-free: __device__ globals) --------------
__device__ float g_h   [NPTS * HID];
__device__ float g_tmp [NPTS * HID];
__device__ float g_c1  [NPTS * (HID / 2)];
__device__ int   g_nidx[NPTS * KNB];
__device__ float g_nw  [NPTS * KNB];

// bf16 split operand buffers (padded rows so tail-tile cp.async stays in-bounds)
__device__ __nv_bfloat16 g_ah[MPAD * HID], g_al[MPAD * HID];   // h split
__device__ __nv_bfloat16 g_gh[MPAD * HID], g_gl[MPAD * HID];   // agg split
#define WTOT 360448
#define WENC 65536
__device__ __nv_bfloat16 g_wh[WTOT], g_wl[WTOT];
// slots: enc=0, g1ws=65536, g1wn=131072, g2ws=196608, g2wn=262144, cls=327680

// grid-knn scratch
__device__ unsigned int g_bbox[4];
__device__ int    g_cellcnt [NCELL + 1];
__device__ int    g_cellstart[NCELL + 1];
__device__ float2 g_pts [NPTS];
__device__ int    g_sidx[NPTS];

__device__ __forceinline__ float gelu_f(float x) {
    return 0.5f * x * (1.0f + erff(x * 0.70710678118654752440f));
}

__device__ __forceinline__ unsigned int fenc(float f) {
    unsigned int u = __float_as_uint(f);
    return (u & 0x80000000u) ? ~u : (u | 0x80000000u);
}
__device__ __forceinline__ float fdec(unsigned int u) {
    return __uint_as_float((u & 0x80000000u) ? (u ^ 0x80000000u) : ~u);
}

__device__ __forceinline__ uint32_t smem_u32(const void* p) {
    uint32_t a;
    asm("{ .reg .u64 t; cvta.to.shared.u64 t, %1; cvt.u32.u64 %0, t; }" : "=r"(a) : "l"(p));
    return a;
}
__device__ __forceinline__ void cpa16(__nv_bfloat16* dst, const __nv_bfloat16* src) {
    const uint32_t d = smem_u32(dst);
    asm volatile("cp.async.cg.shared.global [%0], [%1], 16;" :: "r"(d), "l"(src) : "memory");
}
__device__ __forceinline__ void ldsm_x4(uint32_t* r, uint32_t addr) {
    asm volatile("ldmatrix.sync.aligned.m8n8.x4.shared.b16 {%0,%1,%2,%3}, [%4];"
                 : "=r"(r[0]), "=r"(r[1]), "=r"(r[2]), "=r"(r[3]) : "r"(addr));
}

// HMMA: D(f32) += A(bf16,row) * B(bf16,col), m16n8k16
__device__ __forceinline__ void mma16816(float* c, const uint32_t* a, const uint32_t* b) {
    asm volatile(
        "mma.sync.aligned.m16n8k16.row.col.f32.bf16.bf16.f32 "
        "{%0,%1,%2,%3}, {%4,%5,%6,%7}, {%8,%9}, {%0,%1,%2,%3};"
        : "+f"(c[0]), "+f"(c[1]), "+f"(c[2]), "+f"(c[3])
        : "r"(a[0]), "r"(a[1]), "r"(a[2]), "r"(a[3]), "r"(b[0]), "r"(b[1]));
}

// ================= KNN ========================================================
__global__ void knn_init_kernel() {
    const int t = blockIdx.x * blockDim.x + threadIdx.x;
    if (t <= NCELL) { g_cellcnt[t] = 0; }
    if (t == 0) {
        g_bbox[0] = 0xFFFFFFFFu; g_bbox[1] = 0u;
        g_bbox[2] = 0xFFFFFFFFu; g_bbox[3] = 0u;
    }
}

__global__ void knn_bbox_kernel(const float* __restrict__ cents) {
    const int i = blockIdx.x * blockDim.x + threadIdx.x;
    if (i >= NPTS) return;
    const float x = cents[2 * i], y = cents[2 * i + 1];
    atomicMin(&g_bbox[0], fenc(x));
    atomicMax(&g_bbox[1], fenc(x));
    atomicMin(&g_bbox[2], fenc(y));
    atomicMax(&g_bbox[3], fenc(y));
}

__device__ __forceinline__ void grid_params(float& xmin, float& ymin,
                                            float& iwx, float& iwy,
                                            float& wx, float& wy) {
    xmin = fdec(g_bbox[0]);
    const float xmax = fdec(g_bbox[1]);
    ymin = fdec(g_bbox[2]);
    const float ymax = fdec(g_bbox[3]);
    const float rx = fmaxf(xmax - xmin, 1e-20f);
    const float ry = fmaxf(ymax - ymin, 1e-20f);
    iwx = (float)G / rx; iwy = (float)G / ry;
    wx = rx / (float)G;  wy = ry / (float)G;
}

__device__ __forceinline__ int cell_x(float x, float xmin, float iwx) {
    int c = (int)((x - xmin) * iwx);
    return min(max(c, 0), G - 1);
}

__global__ void knn_count_kernel(const float* __restrict__ cents) {
    const int i = blockIdx.x * blockDim.x + threadIdx.x;
    if (i >= NPTS) return;
    float xmin, ymin, iwx, iwy, wx, wy;
    grid_params(xmin, ymin, iwx, iwy, wx, wy);
    const int cx = cell_x(cents[2 * i],     xmin, iwx);
    const int cy = cell_x(cents[2 * i + 1], ymin, iwy);
    atomicAdd(&g_cellcnt[cy * G + cx], 1);
}

__global__ void knn_scan_kernel() {
    __shared__ int wsum[8];
    const int t = threadIdx.x;
    const int lane = t & 31;
    const int warp = t >> 5;
    const int base = t * 16;
    int c16[16];
#pragma unroll
    for (int q = 0; q < 4; ++q)
        *reinterpret_cast<int4*>(&c16[q * 4]) =
            *reinterpret_cast<const int4*>(&g_cellcnt[base + q * 4]);
    int loc[16];
    int s = 0;
#pragma unroll
    for (int j = 0; j < 16; ++j) { loc[j] = s; s += c16[j]; }
    int v = s;
#pragma unroll
    for (int off = 1; off < 32; off <<= 1) {
        const int n = __shfl_up_sync(0xffffffffu, v, off);
        if (lane >= off) v += n;
    }
    if (lane == 31) wsum[warp] = v;
    __syncthreads();
    if (t == 0) {
        int run = 0;
        for (int i = 0; i < 8; ++i) { const int tmp = wsum[i]; wsum[i] = run; run += tmp; }
    }
    __syncthreads();
    const int pre = wsum[warp] + (v - s);
#pragma unroll
    for (int j = 0; j < 16; ++j) loc[j] += pre;
#pragma unroll
    for (int q = 0; q < 4; ++q) {
        *reinterpret_cast<int4*>(&g_cellstart[base + q * 4]) =
            *reinterpret_cast<const int4*>(&loc[q * 4]);
        *reinterpret_cast<int4*>(&g_cellcnt[base + q * 4]) =
            *reinterpret_cast<const int4*>(&loc[q * 4]);
    }
    if (t == 255) g_cellstart[NCELL] = NPTS;
}

__global__ void knn_scatter_kernel(const float* __restrict__ cents) {
    const int i = blockIdx.x * blockDim.x + threadIdx.x;
    if (i >= NPTS) return;
    float xmin, ymin, iwx, iwy, wx, wy;
    grid_params(xmin, ymin, iwx, iwy, wx, wy);
    const float x = cents[2 * i], y = cents[2 * i + 1];
    const int cx = cell_x(x, xmin, iwx);
    const int cy = cell_x(y, ymin, iwy);
    const int slot = atomicAdd(&g_cellcnt[cy * G + cx], 1);
    g_pts [slot] = make_float2(x, y);
    g_sidx[slot] = i;
}

__global__ void knn_query_kernel(int* __restrict__ nidx, float* __restrict__ nw) {
    const int w = (blockIdx.x * blockDim.x + threadIdx.x) >> 5;
    const int lane = threadIdx.x & 31;
    if (w >= NPTS) return;
    const int s = w;
    const float2 q = g_pts[s];
    const int i = g_sidx[s];

    float xmin, ymin, iwx, iwy, wx, wy;
    grid_params(xmin, ymin, iwx, iwy, wx, wy);
    const int cx = cell_x(q.x, xmin, iwx);
    const int cy = cell_x(q.y, ymin, iwy);

    float vals[KNB];
    int   ids [KNB];
#pragma unroll
    for (int t = 0; t < KNB; ++t) { vals[t] = FLT_MAX; ids[t] = 0; }
    float maxv = FLT_MAX;
    int   maxslot = 0;

    for (int r = 0; r < G; ++r) {
        const int ylo = max(cy - r, 0), yhi = min(cy + r, G - 1);
        for (int vy = ylo; vy <= yhi; ++vy) {
            const bool edge_row = (vy == cy - r) || (vy == cy + r);
            int ps0 = 0, pe0 = 0, ps1 = 0, pe1 = 0;
            if (edge_row) {
                const int xl = max(cx - r, 0), xh = min(cx + r, G - 1);
                ps0 = g_cellstart[vy * G + xl];
                pe0 = g_cellstart[vy * G + xh + 1];
            } else {
                if (cx - r >= 0) {
                    ps0 = g_cellstart[vy * G + cx - r];
                    pe0 = g_cellstart[vy * G + cx - r + 1];
                }
                if (cx + r <= G - 1) {
                    ps1 = g_cellstart[vy * G + cx + r];
                    pe1 = g_cellstart[vy * G + cx + r + 1];
                }
            }
#pragma unroll
            for (int seg = 0; seg < 2; ++seg) {
                const int ps = seg ? ps1 : ps0;
                const int pe = seg ? pe1 : pe0;
                for (int p0 = ps; p0 < pe; p0 += 32) {
                    const int p = p0 + lane;
                    float d2 = FLT_MAX;
                    if (p < pe && p != s) {
                        const float2 f = g_pts[p];
                        const float dx = q.x - f.x;
                        const float dy = q.y - f.y;
                        d2 = fmaf(dx, dx, dy * dy);
                    }
                    unsigned int m = __ballot_sync(0xffffffffu, d2 < maxv);
                    while (m) {
                        const int l = __ffs(m) - 1;
                        m &= m - 1;
                        const float dd = __shfl_sync(0xffffffffu, d2, l);
                        if (dd < maxv) {
                            const int pp = __shfl_sync(0xffffffffu, p, l);
#pragma unroll
                            for (int t = 0; t < KNB; ++t)
                                if (t == maxslot) { vals[t] = dd; ids[t] = pp; }
                            maxv = vals[0]; maxslot = 0;
#pragma unroll
                            for (int t = 1; t < KNB; ++t)
                                if (vals[t] > maxv) { maxv = vals[t]; maxslot = t; }
                        }
                    }
                }
            }
        }
        if (maxv < FLT_MAX) {
            const float bl = (cx - r > 0)     ? q.x - (xmin + (float)(cx - r) * wx)     : FLT_MAX;
            const float br = (cx + r < G - 1) ? (xmin + (float)(cx + r + 1) * wx) - q.x : FLT_MAX;
            const float bb = (cy - r > 0)     ? q.y - (ymin + (float)(cy - r) * wy)     : FLT_MAX;
            const float bt = (cy + r < G - 1) ? (ymin + (float)(cy + r + 1) * wy) - q.y : FLT_MAX;
            const float b = fminf(fminf(bl, br), fminf(bb, bt));
            if (b == FLT_MAX || (b > 0.0f && b * b > maxv)) break;
        }
    }

    int myslot = 0;
#pragma unroll
    for (int t = 0; t < KNB; ++t)
        if (t == lane) myslot = ids[t];

    float invd = 0.0f;
    int oid = 0;
    if (lane < KNB) {
        const float2 f = g_pts[myslot];
        oid = g_sidx[myslot];
        const float xi = q.x, yi = q.y;
        const float sqi = __fadd_rn(__fmul_rn(xi, xi), __fmul_rn(yi, yi));
        const float sqj = __fadd_rn(__fmul_rn(f.x, f.x), __fmul_rn(f.y, f.y));
        const float dot = __fadd_rn(__fmul_rn(xi, f.x), __fmul_rn(yi, f.y));
        const float d2  = __fsub_rn(__fadd_rn(sqi, sqj), __fmul_rn(2.0f, dot));
        const float dist = sqrtf(fmaxf(d2, 0.0f));
        invd = 1.0f / fmaxf(dist, 1e-4f);
    }
    float tot = invd;
#pragma unroll
    for (int o = 16; o > 0; o >>= 1)
        tot += __shfl_xor_sync(0xffffffffu, tot, o);
    if (lane < KNB) {
        nidx[i * KNB + lane] = oid;
        nw  [i * KNB + lane] = invd / fmaxf(tot, 1e-8f);
    }
}

// ================= weight split (ranged) =======================================
__global__ void split_w_kernel(const float* __restrict__ w0, const float* __restrict__ w1,
                               const float* __restrict__ w2, const float* __restrict__ w3,
                               const float* __restrict__ w4, const float* __restrict__ w5,
                               int lo, int hi) {
    const int i = lo + blockIdx.x * blockDim.x + threadIdx.x;
    if (i >= hi) return;
    float x;
    if      (i < 65536)  x = w0[i];
    else if (i < 131072) x = w1[i - 65536];
    else if (i < 196608) x = w2[i - 131072];
    else if (i < 262144) x = w3[i - 196608];
    else if (i < 327680) x = w4[i - 262144];
    else                 x = w5[i - 327680];
    const __nv_bfloat16 h = __float2bfloat16(x);
    g_wh[i] = h;
    g_wl[i] = __float2bfloat16(x - __bfloat162float(h));
}

// ================= HMMA GEMM, cp.async double-buffered, ldmatrix ==============
// 3-term bf16 split (AhWh + AhWl + AlWh). CTA tile 128x128, 8 warps (2x4),
// per-warp 64x32 via 4x4 m16n8k16 frags. K-chunks of 32, 2-stage pipeline.
#define SPAD 40
#define STILE (128 * SPAD)
template <int NCOLS, bool DUAL, bool BIAS, bool SPLITOUT, bool CONVA>
__global__ __launch_bounds__(256) void hmma_gemm_kernel(
    const __nv_bfloat16* __restrict__ a1h, const __nv_bfloat16* __restrict__ a1l,
    const float* __restrict__ a1f,
    const __nv_bfloat16* __restrict__ w1h, const __nv_bfloat16* __restrict__ w1l,
    const __nv_bfloat16* __restrict__ a2h, const __nv_bfloat16* __restrict__ a2l,
    const __nv_bfloat16* __restrict__ w2h, const __nv_bfloat16* __restrict__ w2l,
    const float* __restrict__ bias, float* __restrict__ outF,
    __nv_bfloat16* __restrict__ outH, __nv_bfloat16* __restrict__ outL, int M) {
    extern __shared__ __nv_bfloat16 smem[];

    const int tid  = threadIdx.x;
    const int wid  = tid >> 5;
    const int lane = tid & 31;
    const int gid  = lane >> 2;
    const int tig  = lane & 3;
    const int m0 = blockIdx.x * 128;
    const int n0 = blockIdx.y * 128;
    const int mw = (wid >> 2) * 64;
    const int nw = (wid & 3) * 32;
    const int nchunks = DUAL ? 16 : 8;

    // ldmatrix lane-address components (bytes)
    // A x4: matrix0 rows0-7/k+0, m1 rows8-15/k+0, m2 rows0-7/k+8, m3 rows8-15/k+8
    const uint32_t aLane = (uint32_t)(((mw + (lane & 15)) * SPAD + ((lane >> 4) & 1) * 8) * 2);
    // B x4: m0 n(nj)/k+0, m1 n(nj)/k+8, m2 n(nj+1)/k+0, m3 n(nj+1)/k+8
    const uint32_t bLane = (uint32_t)(((nw + 8 * ((lane >> 4) & 1) + (lane & 7)) * SPAD +
                                       ((lane >> 3) & 1) * 8) * 2);

    float acc[4][4][4];
#pragma unroll
    for (int a = 0; a < 4; ++a)
#pragma unroll
        for (int b = 0; b < 4; ++b)
#pragma unroll
            for (int c = 0; c < 4; ++c) acc[a][b][c] = 0.0f;

    auto stage = [&](int c) {
        const int k0 = (c & 7) * 32;
        const bool s1 = DUAL && (c >= 8);
        const __nv_bfloat16* Ah = s1 ? a2h : a1h;
        const __nv_bfloat16* Al = s1 ? a2l : a1l;
        const __nv_bfloat16* Wh = s1 ? w2h : w1h;
        const __nv_bfloat16* Wl = s1 ? w2l : w1l;
        __nv_bfloat16* buf = smem + (c & 1) * 4 * STILE;
        __nv_bfloat16* bAh = buf;
        __nv_bfloat16* bAl = buf + STILE;
        __nv_bfloat16* bBh = buf + 2 * STILE;
        __nv_bfloat16* bBl = buf + 3 * STILE;
#pragma unroll
        for (int u = tid; u < 512; u += 256) {
            const int r = u >> 2, qd = u & 3;
            const int off = r * SPAD + qd * 8;
            cpa16(bBh + off, Wh + (size_t)(n0 + r) * HID + k0 + qd * 8);
            cpa16(bBl + off, Wl + (size_t)(n0 + r) * HID + k0 + qd * 8);
            if (CONVA) {
                const int mg = m0 + r;
                __align__(16) __nv_bfloat16 hh[8], ll[8];
                if (mg < M) {
                    const float* fp = a1f + (size_t)mg * HID + k0 + qd * 8;
                    const float4 f0 = *reinterpret_cast<const float4*>(fp);
                    const float4 f1 = *reinterpret_cast<const float4*>(fp + 4);
                    const float fv[8] = {f0.x, f0.y, f0.z, f0.w, f1.x, f1.y, f1.z, f1.w};
#pragma unroll
                    for (int j = 0; j < 8; ++j) {
                        hh[j] = __float2bfloat16(fv[j]);
                        ll[j] = __float2bfloat16(fv[j] - __bfloat162float(hh[j]));
                    }
                } else {
#pragma unroll
                    for (int j = 0; j < 8; ++j) { hh[j] = __nv_bfloat16(0.f); ll[j] = __nv_bfloat16(0.f); }
                }
                *reinterpret_cast<uint4*>(bAh + off) = *reinterpret_cast<const uint4*>(hh);
                *reinterpret_cast<uint4*>(bAl + off) = *reinterpret_cast<const uint4*>(ll);
            } else {
                cpa16(bAh + off, Ah + (size_t)(m0 + r) * HID + k0 + qd * 8);
                cpa16(bAl + off, Al + (size_t)(m0 + r) * HID + k0 + qd * 8);
            }
        }
        asm volatile("cp.async.commit_group;" ::: "memory");
    };

    stage(0);
    for (int c = 0; c < nchunks; ++c) {
        if (c + 1 < nchunks) {
            stage(c + 1);
            asm volatile("cp.async.wait_group 1;" ::: "memory");
        } else {
            asm volatile("cp.async.wait_group 0;" ::: "memory");
        }
        __syncthreads();

        const uint32_t bufB = smem_u32(smem + (c & 1) * 4 * STILE);
        const uint32_t aH = bufB + aLane;
        const uint32_t aL = bufB + STILE * 2 + aLane;
        const uint32_t bH = bufB + 2 * STILE * 2 + bLane;
        const uint32_t bL = bufB + 3 * STILE * 2 + bLane;

#pragma unroll
        for (int kk = 0; kk < 32; kk += 16) {
            uint32_t afh[4][4], afl[4][4];
#pragma unroll
            for (int mi = 0; mi < 4; ++mi) {
                ldsm_x4(afh[mi], aH + (uint32_t)(mi * 32 * SPAD + 2 * kk));
                ldsm_x4(afl[mi], aL + (uint32_t)(mi * 32 * SPAD + 2 * kk));
            }
#pragma unroll
            for (int njp = 0; njp < 2; ++njp) {
                uint32_t bh[4], bl[4];
                ldsm_x4(bh, bH + (uint32_t)(njp * 32 * SPAD + 2 * kk));
                ldsm_x4(bl, bL + (uint32_t)(njp * 32 * SPAD + 2 * kk));
#pragma unroll
                for (int mi = 0; mi < 4; ++mi) {
                    mma16816(acc[mi][2 * njp],     afh[mi], bh);
                    mma16816(acc[mi][2 * njp],     afh[mi], bl);
                    mma16816(acc[mi][2 * njp],     afl[mi], bh);
                    mma16816(acc[mi][2 * njp + 1], afh[mi], bh + 2);
                    mma16816(acc[mi][2 * njp + 1], afh[mi], bl + 2);
                    mma16816(acc[mi][2 * njp + 1], afl[mi], bh + 2);
                }
            }
        }
        __syncthreads();
    }

    // epilogue: bias + gelu (+ bf16 split)
#pragma unroll
    for (int mi = 0; mi < 4; ++mi) {
#pragma unroll
        for (int half = 0; half < 2; ++half) {
            const int m = m0 + mw + 16 * mi + gid + 8 * half;
            if (m >= M) continue;
#pragma unroll
            for (int nj = 0; nj < 4; ++nj) {
                const int ng = n0 + nw + 8 * nj + tig * 2;
                float v0 = acc[mi][nj][2 * half + 0];
                float v1 = acc[mi][nj][2 * half + 1];
                if (BIAS) { v0 += bias[ng]; v1 += bias[ng + 1]; }
                v0 = gelu_f(v0);
                v1 = gelu_f(v1);
                *reinterpret_cast<float2*>(outF + (size_t)m * NCOLS + ng) =
                    make_float2(v0, v1);
                if (SPLITOUT) {
                    const __nv_bfloat16 h0 = __float2bfloat16(v0);
                    const __nv_bfloat16 h1 = __float2bfloat16(v1);
                    outH[(size_t)m * 256 + ng]     = h0;
                    outH[(size_t)m * 256 + ng + 1] = h1;
                    outL[(size_t)m * 256 + ng]     = __float2bfloat16(v0 - __bfloat162float(h0));
                    outL[(size_t)m * 256 + ng + 1] = __float2bfloat16(v1 - __bfloat162float(h1));
                }
            }
        }
    }
}

// ================= neighbor aggregation (emits bf16 split) ====================
__global__ void agg_kernel(const float* __restrict__ h, const int* __restrict__ nidx,
                           const float* __restrict__ nw,
                           __nv_bfloat16* __restrict__ gh, __nv_bfloat16* __restrict__ gl) {
    const int n = blockIdx.x;
    const int d = threadIdx.x;
    __shared__ int   sidx[KNB];
    __shared__ float sw  [KNB];
    if (d < KNB) { sidx[d] = nidx[n * KNB + d]; sw[d] = nw[n * KNB + d]; }
    __syncthreads();
    float acc = 0.0f;
#pragma unroll
    for (int k = 0; k < KNB; ++k)
        acc = fmaf(sw[k], h[(size_t)sidx[k] * HID + d], acc);
    const __nv_bfloat16 hi = __float2bfloat16(acc);
    gh[(size_t)n * HID + d] = hi;
    gl[(size_t)n * HID + d] = __float2bfloat16(acc - __bfloat162float(hi));
}

// ================= layernorm + residual (emits fp32 + bf16 split) =============
__global__ void ln_res_kernel(const float* __restrict__ x, const float* __restrict__ g,
                              const float* __restrict__ b, float* __restrict__ h,
                              __nv_bfloat16* __restrict__ ah, __nv_bfloat16* __restrict__ al) {
    const int n = blockIdx.x;
    const int d = threadIdx.x;
    __shared__ float red[8];
    __shared__ float s_mu, s_rstd;

    const float v = x[(size_t)n * HID + d];
    float s = v;
#pragma unroll
    for (int o = 16; o > 0; o >>= 1) s += __shfl_xor_sync(0xffffffffu, s, o);
    if ((d & 31) == 0) red[d >> 5] = s;
    __syncthreads();
    if (d == 0) {
        float t = 0.0f;
        for (int i = 0; i < 8; ++i) t += red[i];
        s_mu = t * (1.0f / HID);
    }
    __syncthreads();
    const float mu = s_mu;
    const float df = v - mu;
    float q = df * df;
#pragma unroll
    for (int o = 16; o > 0; o >>= 1) q += __shfl_xor_sync(0xffffffffu, q, o);
    __syncthreads();
    if ((d & 31) == 0) red[d >> 5] = q;
    __syncthreads();
    if (d == 0) {
        float t = 0.0f;
        for (int i = 0; i < 8; ++i) t += red[i];
        s_rstd = rsqrtf(t * (1.0f / HID) + 1e-5f);
    }
    __syncthreads();
    const float hv = h[(size_t)n * HID + d] + df * s_rstd * g[d] + b[d];
    h[(size_t)n * HID + d] = hv;
    const __nv_bfloat16 hi = __float2bfloat16(hv);
    ah[(size_t)n * HID + d] = hi;
    al[(size_t)n * HID + d] = __float2bfloat16(hv - __bfloat162float(hi));
}

// ================= classifier layer 2 + sigmoid ================================
__global__ void cls2_kernel(const float* __restrict__ c1, const float* __restrict__ w2,
                            const float* __restrict__ b2, float* __restrict__ out, int M) {
    const int warp = threadIdx.x >> 5;
    const int lane = threadIdx.x & 31;
    const int r = blockIdx.x * 8 + warp;
    if (r >= M) return;
    float s = 0.0f;
#pragma unroll
    for (int j0 = 0; j0 < 128; j0 += 32)
        s = fmaf(c1[(size_t)r * 128 + j0 + lane], w2[j0 + lane], s);
#pragma unroll
    for (int o = 16; o > 0; o >>= 1) s += __shfl_xor_sync(0xffffffffu, s, o);
    if (lane == 0) {
        const float logit = s + b2[0];
        out[r] = 1.0f / (1.0f + expf(-logit));
    }
}

// ================= launch =======================================================
extern "C" void kernel_launch(void* const* d_in, const int* in_sizes, int n_in,
                              void* d_out, int out_size) {
    const float* feats  = (const float*)d_in[0];
    const float* cents  = (const float*)d_in[1];
    const float* enc_w  = (const float*)d_in[2];
    const float* enc_b  = (const float*)d_in[3];
    const float* g1_ws  = (const float*)d_in[4];
    const float* g1_wn  = (const float*)d_in[5];
    const float* g1_g   = (const float*)d_in[6];
    const float* g1_b   = (const float*)d_in[7];
    const float* g2_ws  = (const float*)d_in[8];
    const float* g2_wn  = (const float*)d_in[9];
    const float* g2_g   = (const float*)d_in[10];
    const float* g2_b   = (const float*)d_in[11];
    const float* cls_w1 = (const float*)d_in[12];
    const float* cls_b1 = (const float*)d_in[13];
    const float* cls_w2 = (const float*)d_in[14];
    const float* cls_b2 = (const float*)d_in[15];
    float* out = (float*)d_out;

    float *p_h, *p_tmp, *p_c1, *p_nw;
    int* p_nidx;
    __nv_bfloat16 *p_ah, *p_al, *p_gh, *p_gl, *p_wh, *p_wl;
    cudaGetSymbolAddress((void**)&p_h,    g_h);
    cudaGetSymbolAddress((void**)&p_tmp,  g_tmp);
    cudaGetSymbolAddress((void**)&p_c1,   g_c1);
    cudaGetSymbolAddress((void**)&p_nidx, g_nidx);
    cudaGetSymbolAddress((void**)&p_nw,   g_nw);
    cudaGetSymbolAddress((void**)&p_ah,   g_ah);
    cudaGetSymbolAddress((void**)&p_al,   g_al);
    cudaGetSymbolAddress((void**)&p_gh,   g_gh);
    cudaGetSymbolAddress((void**)&p_gl,   g_gl);
    cudaGetSymbolAddress((void**)&p_wh,   g_wh);
    cudaGetSymbolAddress((void**)&p_wl,   g_wl);

    const int M = NPTS;
    const int NBLK = (M + 127) / 128;   // 94
    const dim3 gFull(NBLK, 2);
    const dim3 gHalf(NBLK, 1);
    const int SMEM_DYN = 2 * 4 * STILE * (int)sizeof(__nv_bfloat16);  // 81920

    cudaFuncSetAttribute(hmma_gemm_kernel<256, false, true,  true,  true >,
                         cudaFuncAttributeMaxDynamicSharedMemorySize, SMEM_DYN);
    cudaFuncSetAttribute(hmma_gemm_kernel<256, true,  false, false, false>,
                         cudaFuncAttributeMaxDynamicSharedMemorySize, SMEM_DYN);
    cudaFuncSetAttribute(hmma_gemm_kernel<128, false, true,  false, false>,
                         cudaFuncAttributeMaxDynamicSharedMemorySize, SMEM_DYN);

    // ---- fork: KNN chain + non-encoder weight split on s2 ----
    cudaStream_t s2;
    cudaStreamCreateWithFlags(&s2, cudaStreamNonBlocking);
    cudaEvent_t evF, evJ;
    cudaEventCreateWithFlags(&evF, cudaEventDisableTiming);
    cudaEventCreateWithFlags(&evJ, cudaEventDisableTiming);
    cudaEventRecord(evF, 0);
    cudaStreamWaitEvent(s2, evF, 0);

    knn_init_kernel   <<<(NCELL + 256) / 256, 256, 0, s2>>>();
    knn_bbox_kernel   <<<(NPTS + 255) / 256, 256, 0, s2>>>(cents);
    knn_count_kernel  <<<(NPTS + 255) / 256, 256, 0, s2>>>(cents);
    knn_scan_kernel   <<<1, 256, 0, s2>>>();
    knn_scatter_kernel<<<(NPTS + 255) / 256, 256, 0, s2>>>(cents);
    knn_query_kernel  <<<(NPTS * 32 + 255) / 256, 256, 0, s2>>>(p_nidx, p_nw);
    // split non-encoder weights on s2 (idle after query issues)
    split_w_kernel<<<(WTOT - WENC + 255) / 256, 256, 0, s2>>>(
        enc_w, g1_ws, g1_wn, g2_ws, g2_wn, cls_w1, WENC, WTOT);
    cudaEventRecord(evJ, s2);

    // main stream: encoder weight split + encoder (feats converted in-kernel)
    split_w_kernel<<<(WENC + 255) / 256, 256>>>(
        enc_w, g1_ws, g1_wn, g2_ws, g2_wn, cls_w1, 0, WENC);
    hmma_gemm_kernel<256, false, true, true, true><<<gFull, 256, SMEM_DYN>>>(
        nullptr, nullptr, feats, p_wh + 0, p_wl + 0,
        nullptr, nullptr, nullptr, nullptr,
        enc_b, p_h, p_ah, p_al, M);

    // join: agg needs knn graph; gemm1 needs remaining weight splits
    cudaStreamWaitEvent(0, evJ, 0);

    // SAGE layer 1
    agg_kernel<<<NPTS, HID>>>(p_h, p_nidx, p_nw, p_gh, p_gl);
    hmma_gemm_kernel<256, true, false, false, false><<<gFull, 256, SMEM_DYN>>>(
        p_ah, p_al, nullptr, p_wh + 65536, p_wl + 65536,
        p_gh, p_gl, p_wh + 131072, p_wl + 131072,
        nullptr, p_tmp, nullptr, nullptr, M);
    ln_res_kernel<<<NPTS, HID>>>(p_tmp, g1_g, g1_b, p_h, p_ah, p_al);

    // SAGE layer 2
    agg_kernel<<<NPTS, HID>>>(p_h, p_nidx, p_nw, p_gh, p_gl);
    hmma_gemm_kernel<256, true, false, false, false><<<gFull, 256, SMEM_DYN>>>(
        p_ah, p_al, nullptr, p_wh + 196608, p_wl + 196608,
        p_gh, p_gl, p_wh + 262144, p_wl + 262144,
        nullptr, p_tmp, nullptr, nullptr, M);
    ln_res_kernel<<<NPTS, HID>>>(p_tmp, g2_g, g2_b, p_h, p_ah, p_al);

    // classifier
    hmma_gemm_kernel<128, false, true, false, false><<<gHalf, 256, SMEM_DYN>>>(
        p_ah, p_al, nullptr, p_wh + 327680, p_wl + 327680,
        nullptr, nullptr, nullptr, nullptr,
        cls_b1, p_c1, nullptr, nullptr, M);
    cls2_kernel<<<(M + 7) / 8, 256>>>(p_c1, cls_w2, cls_b2, out, M);
}